// round 6
// baseline (speedup 1.0000x reference)
#include <cuda_runtime.h>
#include <cuda_bf16.h>
#include <cuda_fp16.h>
#include <math.h>
#include <stdint.h>

#define NN 100000
#define EE 1600000
#define NBLK_SCAN ((NN + 1023) / 1024)

// ---------------- device scratch (no allocations allowed) ----------------
__device__ int g_deg[NN];
__device__ int g_rowptr[NN + 1];
__device__ int g_fill[NN];
__device__ int g_csr[EE];
__device__ int g_blksum[NBLK_SCAN];

__device__ __half g_xh[(size_t)NN * 128];
__device__ float  g_agg[(size_t)NN * 128];
__device__ float  g_h1[(size_t)NN * 128];
__device__ __half g_h1h[(size_t)NN * 128];
__device__ float  g_h2[(size_t)NN * 128];
__device__ __half g_t3h[(size_t)NN * 64];
__device__ float  g_agg3[(size_t)NN * 64];
__device__ float  g_r3[(size_t)NN * 64];

// ---------------- CSR construction ----------------
__global__ void k_hist(const int* __restrict__ dst, int E) {
    int e = blockIdx.x * blockDim.x + threadIdx.x;
    if (e < E) atomicAdd(&g_deg[dst[e]], 1);
}

__global__ void k_scan1() {
    __shared__ int s[1024];
    int i = threadIdx.x;
    int gid = blockIdx.x * 1024 + i;
    int v = (gid < NN) ? g_deg[gid] : 0;
    s[i] = v;
    __syncthreads();
    for (int off = 1; off < 1024; off <<= 1) {
        int add = (i >= off) ? s[i - off] : 0;
        __syncthreads();
        s[i] += add;
        __syncthreads();
    }
    if (gid < NN) g_rowptr[gid] = s[i] - v;
    if (i == 1023) g_blksum[blockIdx.x] = s[1023];
}

__global__ void k_scan2() {
    __shared__ int s[128];
    int i = threadIdx.x;
    int v = (i < NBLK_SCAN) ? g_blksum[i] : 0;
    s[i] = v;
    __syncthreads();
    for (int off = 1; off < 128; off <<= 1) {
        int a = (i >= off) ? s[i - off] : 0;
        __syncthreads();
        s[i] += a;
        __syncthreads();
    }
    if (i < NBLK_SCAN) g_blksum[i] = s[i] - v;
}

__global__ void k_scan3(int E) {
    int gid = blockIdx.x * blockDim.x + threadIdx.x;
    if (gid < NN) {
        int rp = g_rowptr[gid] + g_blksum[gid >> 10];
        g_rowptr[gid] = rp;
        g_fill[gid] = rp;
        g_deg[gid] = 0;   // pre-zero for the NEXT call
    } else if (gid == NN) {
        g_rowptr[NN] = E;
    }
}

__global__ void k_scatter(const int* __restrict__ src, const int* __restrict__ dst, int E) {
    int e = blockIdx.x * blockDim.x + threadIdx.x;
    if (e < E) {
        int p = atomicAdd(&g_fill[dst[e]], 1);
        g_csr[p] = src[e];
    }
}

// ---------------- x -> fp16 shadow ----------------
__global__ void k_x2h(const float* __restrict__ x, __half* __restrict__ xh) {
    int i = blockIdx.x * blockDim.x + threadIdx.x;
    if (i < NN * 32) {
        float4 v = ((const float4*)x)[i];
        __half2* o = (__half2*)xh + 2 * i;
        o[0] = __float22half2_rn(make_float2(v.x, v.y));
        o[1] = __float22half2_rn(make_float2(v.z, v.w));
    }
}

// ---------------- mean aggregation over fp16 rows (warp per node) ----------------
__device__ __forceinline__ void acc_h4(uint2 u, float* acc) {
    float2 f0 = __half22float2(*(__half2*)&u.x);
    float2 f1 = __half22float2(*(__half2*)&u.y);
    acc[0] += f0.x; acc[1] += f0.y; acc[2] += f1.x; acc[3] += f1.y;
}

__global__ void k_aggr128h(const __half* __restrict__ xh, float* __restrict__ out) {
    int wid = blockIdx.x * (blockDim.x >> 5) + (threadIdx.x >> 5);
    int lane = threadIdx.x & 31;
    if (wid >= NN) return;
    int beg = g_rowptr[wid], end = g_rowptr[wid + 1];
    const uint2* base = (const uint2*)xh;
    float acc[4] = {0.f, 0.f, 0.f, 0.f};
    int j = beg;
    for (; j + 3 < end; j += 4) {
        int s0 = g_csr[j], s1 = g_csr[j + 1], s2 = g_csr[j + 2], s3 = g_csr[j + 3];
        uint2 u0 = base[(size_t)s0 * 32 + lane];
        uint2 u1 = base[(size_t)s1 * 32 + lane];
        uint2 u2 = base[(size_t)s2 * 32 + lane];
        uint2 u3 = base[(size_t)s3 * 32 + lane];
        acc_h4(u0, acc); acc_h4(u1, acc); acc_h4(u2, acc); acc_h4(u3, acc);
    }
    for (; j < end; j++) {
        uint2 u0 = base[(size_t)g_csr[j] * 32 + lane];
        acc_h4(u0, acc);
    }
    float inv = 1.f / fmaxf((float)(end - beg), 1.f);
    *(float4*)(out + (size_t)wid * 128 + lane * 4) =
        make_float4(acc[0] * inv, acc[1] * inv, acc[2] * inv, acc[3] * inv);
}

__global__ void k_aggr64h(const __half* __restrict__ xh, float* __restrict__ out) {
    int wid = blockIdx.x * (blockDim.x >> 5) + (threadIdx.x >> 5);
    int lane = threadIdx.x & 31;
    if (wid >= NN) return;
    int beg = g_rowptr[wid], end = g_rowptr[wid + 1];
    const unsigned* base = (const unsigned*)xh;
    float a0 = 0.f, a1 = 0.f;
    int j = beg;
    for (; j + 3 < end; j += 4) {
        int s0 = g_csr[j], s1 = g_csr[j + 1], s2 = g_csr[j + 2], s3 = g_csr[j + 3];
        unsigned u0 = base[(size_t)s0 * 32 + lane];
        unsigned u1 = base[(size_t)s1 * 32 + lane];
        unsigned u2 = base[(size_t)s2 * 32 + lane];
        unsigned u3 = base[(size_t)s3 * 32 + lane];
        float2 f0 = __half22float2(*(__half2*)&u0);
        float2 f1 = __half22float2(*(__half2*)&u1);
        float2 f2 = __half22float2(*(__half2*)&u2);
        float2 f3 = __half22float2(*(__half2*)&u3);
        a0 += (f0.x + f1.x) + (f2.x + f3.x);
        a1 += (f0.y + f1.y) + (f2.y + f3.y);
    }
    for (; j < end; j++) {
        unsigned u0 = base[(size_t)g_csr[j] * 32 + lane];
        float2 f0 = __half22float2(*(__half2*)&u0);
        a0 += f0.x; a1 += f0.y;
    }
    float inv = 1.f / fmaxf((float)(end - beg), 1.f);
    *(float2*)(out + (size_t)wid * 64 + lane * 2) = make_float2(a0 * inv, a1 * inv);
}

// ---------------- bf16 split helpers ----------------
__device__ __forceinline__ void bfsplit2(float v0, float v1, unsigned& hi, unsigned& lo) {
    __nv_bfloat16 h0 = __float2bfloat16(v0);
    __nv_bfloat16 h1 = __float2bfloat16(v1);
    float r0 = v0 - __bfloat162float(h0);
    float r1 = v1 - __bfloat162float(h1);
    __nv_bfloat16 l0 = __float2bfloat16(r0);
    __nv_bfloat16 l1 = __float2bfloat16(r1);
    hi = ((unsigned)__bfloat16_as_ushort(h1) << 16) | (unsigned)__bfloat16_as_ushort(h0);
    lo = ((unsigned)__bfloat16_as_ushort(l1) << 16) | (unsigned)__bfloat16_as_ushort(l0);
}

#define MMA_BF16(C, A, b0, b1)                                                \
    asm volatile(                                                             \
        "mma.sync.aligned.m16n8k16.row.col.f32.bf16.bf16.f32 "                \
        "{%0,%1,%2,%3},{%4,%5,%6,%7},{%8,%9},{%0,%1,%2,%3};"                  \
        : "+f"((C)[0]), "+f"((C)[1]), "+f"((C)[2]), "+f"((C)[3])              \
        : "r"((A)[0]), "r"((A)[1]), "r"((A)[2]), "r"((A)[3]),                 \
          "r"(b0), "r"(b1))

// full-tile smem layout: 128 rows x 64 bf16x2 words, row stride 68 words.
// 68 mod 32 = 4 -> fragment read bank = 4g+tg, all 32 lanes distinct.
#define TSW 68
#define TILE_WORDS (128 * TSW)
#define DSMEM (4 * TILE_WORDS * 4)

// convert one row-half (64 floats) into hi/lo bf16x2 words
__device__ __forceinline__ void fill_from(const float* __restrict__ p,
                                          unsigned* dh, unsigned* dl) {
#pragma unroll
    for (int j = 0; j < 8; j++) {
        float4 va = *(const float4*)(p + 8 * j);
        float4 vb = *(const float4*)(p + 8 * j + 4);
        uint4 hi, lo;
        bfsplit2(va.x, va.y, hi.x, lo.x);
        bfsplit2(va.z, va.w, hi.y, lo.y);
        bfsplit2(vb.x, vb.y, hi.z, lo.z);
        bfsplit2(vb.z, vb.w, hi.w, lo.w);
        *(uint4*)(dh + 4 * j) = hi;
        *(uint4*)(dl + 4 * j) = lo;
    }
}

__device__ __forceinline__ void fill_zero(unsigned* dh, unsigned* dl) {
#pragma unroll
    for (int j = 0; j < 8; j++) {
        *(uint4*)(dh + 4 * j) = make_uint4(0, 0, 0, 0);
        *(uint4*)(dl + 4 * j) = make_uint4(0, 0, 0, 0);
    }
}

// run the 8-kstep x 8-nt x 2-mt x 3-term MMA sweep over staged full tiles
__device__ __forceinline__ void mma_sweep(const unsigned* sA_hi, const unsigned* sA_lo,
                                          const unsigned* sW_hi, const unsigned* sW_lo,
                                          float c[2][8][4], int wr, int wc,
                                          int g, int tg) {
#pragma unroll
    for (int ks = 0; ks < 8; ks++) {
        const int kw = ks * 8;
        unsigned ahi[2][4], alo[2][4];
#pragma unroll
        for (int mt = 0; mt < 2; mt++) {
            int r = wr * 32 + mt * 16 + g;
            ahi[mt][0] = sA_hi[r * TSW + kw + tg];
            ahi[mt][1] = sA_hi[(r + 8) * TSW + kw + tg];
            ahi[mt][2] = sA_hi[r * TSW + kw + tg + 4];
            ahi[mt][3] = sA_hi[(r + 8) * TSW + kw + tg + 4];
            alo[mt][0] = sA_lo[r * TSW + kw + tg];
            alo[mt][1] = sA_lo[(r + 8) * TSW + kw + tg];
            alo[mt][2] = sA_lo[r * TSW + kw + tg + 4];
            alo[mt][3] = sA_lo[(r + 8) * TSW + kw + tg + 4];
        }
#pragma unroll
        for (int nt = 0; nt < 8; nt++) {
            int n = wc * 64 + nt * 8 + g;
            unsigned bh0 = sW_hi[n * TSW + kw + tg], bh1 = sW_hi[n * TSW + kw + tg + 4];
            unsigned bl0 = sW_lo[n * TSW + kw + tg], bl1 = sW_lo[n * TSW + kw + tg + 4];
#pragma unroll
            for (int mt = 0; mt < 2; mt++) {
                MMA_BF16(c[mt][nt], ahi[mt], bh0, bh1);
                MMA_BF16(c[mt][nt], ahi[mt], bl0, bl1);
                MMA_BF16(c[mt][nt], alo[mt], bh0, bh1);
            }
        }
    }
}

// ---------------- fused dual GEMM + BN + ReLU (full-tile staging) ----------------
// out = relu( bn( A1@W1^T + A2@W2^T + bias ) )   [NN,128] x [128,128]
__global__ __launch_bounds__(256, 1) void k_gemm_dual_bnrelu(
    const float* __restrict__ A1, const float* __restrict__ W1,
    const float* __restrict__ A2, const float* __restrict__ W2,
    const float* __restrict__ bias, const float* __restrict__ gamma,
    const float* __restrict__ beta, const float* __restrict__ rmean,
    const float* __restrict__ rvar, float* __restrict__ out,
    __half* __restrict__ out16)
{
    extern __shared__ unsigned dyn[];
    unsigned* sA_hi = dyn;
    unsigned* sA_lo = sA_hi + TILE_WORDS;
    unsigned* sW_hi = sA_lo + TILE_WORDS;
    unsigned* sW_lo = sW_hi + TILE_WORDS;
    __shared__ float s_sc[128], s_sh[128];

    const int t = threadIdx.x;
    const int lane = t & 31, wid = t >> 5;
    const int wr = wid & 3, wc = wid >> 2;
    const int g = lane >> 2, tg = lane & 3;
    const int row0 = blockIdx.x * 128;
    const int fr = t >> 1, fh = t & 1;   // fill row, half

    if (t < 128) {
        float s = gamma[t] * rsqrtf(rvar[t] + 1e-5f);
        s_sc[t] = s;
        s_sh[t] = beta[t] + (bias[t] - rmean[t]) * s;
    }

    float c[2][8][4];
#pragma unroll
    for (int mt = 0; mt < 2; mt++)
#pragma unroll
        for (int nt = 0; nt < 8; nt++)
#pragma unroll
            for (int q = 0; q < 4; q++) c[mt][nt][q] = 0.f;

#pragma unroll
    for (int pass = 0; pass < 2; pass++) {
        const float* A = pass ? A2 : A1;
        const float* W = pass ? W2 : W1;
        {
            int gr = row0 + fr;
            unsigned* dh = sA_hi + fr * TSW + fh * 32;
            unsigned* dl = sA_lo + fr * TSW + fh * 32;
            if (gr < NN) fill_from(A + (size_t)gr * 128 + fh * 64, dh, dl);
            else         fill_zero(dh, dl);
            fill_from(W + (size_t)fr * 128 + fh * 64,
                      sW_hi + fr * TSW + fh * 32, sW_lo + fr * TSW + fh * 32);
        }
        __syncthreads();
        mma_sweep(sA_hi, sA_lo, sW_hi, sW_lo, c, wr, wc, g, tg);
        if (pass == 0) __syncthreads();   // protect smem before refill
    }

    // epilogue: BN + ReLU
#pragma unroll
    for (int mt = 0; mt < 2; mt++) {
#pragma unroll
        for (int i = 0; i < 2; i++) {
            int r = row0 + wr * 32 + mt * 16 + g + i * 8;
            if (r >= NN) continue;
#pragma unroll
            for (int nt = 0; nt < 8; nt++) {
                int col = wc * 64 + nt * 8 + 2 * tg;
                float v0 = c[mt][nt][2 * i];
                float v1 = c[mt][nt][2 * i + 1];
                v0 = fmaxf(v0 * s_sc[col] + s_sh[col], 0.f);
                v1 = fmaxf(v1 * s_sc[col + 1] + s_sh[col + 1], 0.f);
                *(float2*)(out + (size_t)r * 128 + col) = make_float2(v0, v1);
                if (out16)
                    *(__half2*)(out16 + (size_t)r * 128 + col) =
                        __float22half2_rn(make_float2(v0, v1));
            }
        }
    }
}

// ---------------- layer-3 combined GEMM: A@[W3l;W3r]^T (full-tile staging) ----------------
__global__ __launch_bounds__(256, 1) void k_gemm3(
    const float* __restrict__ A, const float* __restrict__ Wl,
    const float* __restrict__ Wr, const float* __restrict__ bias,
    __half* __restrict__ t3h, float* __restrict__ r3)
{
    extern __shared__ unsigned dyn[];
    unsigned* sA_hi = dyn;
    unsigned* sA_lo = sA_hi + TILE_WORDS;
    unsigned* sW_hi = sA_lo + TILE_WORDS;
    unsigned* sW_lo = sW_hi + TILE_WORDS;

    const int t = threadIdx.x;
    const int lane = t & 31, wid = t >> 5;
    const int wr = wid & 3, wc = wid >> 2;
    const int g = lane >> 2, tg = lane & 3;
    const int row0 = blockIdx.x * 128;
    const int fr = t >> 1, fh = t & 1;

    float c[2][8][4];
#pragma unroll
    for (int mt = 0; mt < 2; mt++)
#pragma unroll
        for (int nt = 0; nt < 8; nt++)
#pragma unroll
            for (int q = 0; q < 4; q++) c[mt][nt][q] = 0.f;

    {
        int gr = row0 + fr;
        unsigned* dh = sA_hi + fr * TSW + fh * 32;
        unsigned* dl = sA_lo + fr * TSW + fh * 32;
        if (gr < NN) fill_from(A + (size_t)gr * 128 + fh * 64, dh, dl);
        else         fill_zero(dh, dl);
        const float* p = (fr < 64) ? (Wl + (size_t)fr * 128 + fh * 64)
                                   : (Wr + (size_t)(fr - 64) * 128 + fh * 64);
        fill_from(p, sW_hi + fr * TSW + fh * 32, sW_lo + fr * TSW + fh * 32);
    }
    __syncthreads();
    mma_sweep(sA_hi, sA_lo, sW_hi, sW_lo, c, wr, wc, g, tg);

#pragma unroll
    for (int mt = 0; mt < 2; mt++) {
#pragma unroll
        for (int i = 0; i < 2; i++) {
            int r = row0 + wr * 32 + mt * 16 + g + i * 8;
            if (r >= NN) continue;
#pragma unroll
            for (int nt = 0; nt < 8; nt++) {
                int col = wc * 64 + nt * 8 + 2 * tg;   // 0..127
                float v0 = c[mt][nt][2 * i];
                float v1 = c[mt][nt][2 * i + 1];
                if (col < 64) {
                    *(__half2*)(t3h + (size_t)r * 64 + col) =
                        __float22half2_rn(make_float2(v0, v1));
                } else {
                    int cc = col - 64;
                    v0 += bias[cc]; v1 += bias[cc + 1];
                    *(float2*)(r3 + (size_t)r * 64 + cc) = make_float2(v0, v1);
                }
            }
        }
    }
}

// ---------------- final: add + log_softmax over 64 (warp per row) ----------------
__global__ void k_lsm_final(const float* __restrict__ r3, const float* __restrict__ agg3,
                            float* __restrict__ out) {
    int wid = blockIdx.x * (blockDim.x >> 5) + (threadIdx.x >> 5);
    int lane = threadIdx.x & 31;
    if (wid >= NN) return;
    float v0 = r3[(size_t)wid * 64 + lane] + agg3[(size_t)wid * 64 + lane];
    float v1 = r3[(size_t)wid * 64 + 32 + lane] + agg3[(size_t)wid * 64 + 32 + lane];
    float m = fmaxf(v0, v1);
#pragma unroll
    for (int o = 16; o > 0; o >>= 1) m = fmaxf(m, __shfl_xor_sync(0xffffffffu, m, o));
    float s = expf(v0 - m) + expf(v1 - m);
#pragma unroll
    for (int o = 16; o > 0; o >>= 1) s += __shfl_xor_sync(0xffffffffu, s, o);
    float l = m + logf(s);
    out[(size_t)wid * 64 + lane] = v0 - l;
    out[(size_t)wid * 64 + 32 + lane] = v1 - l;
}

// ---------------- launch ----------------
extern "C" void kernel_launch(void* const* d_in, const int* in_sizes, int n_in,
                              void* d_out, int out_size) {
    const float* x   = (const float*)d_in[0];
    const int*   src = (const int*)d_in[1];
    const int*   dst = (const int*)d_in[2];
    const float* W1l = (const float*)d_in[3];
    const float* W1r = (const float*)d_in[4];
    const float* b1  = (const float*)d_in[5];
    const float* g1  = (const float*)d_in[6];
    const float* be1 = (const float*)d_in[7];
    const float* rm1 = (const float*)d_in[8];
    const float* rv1 = (const float*)d_in[9];
    const float* W2l = (const float*)d_in[10];
    const float* W2r = (const float*)d_in[11];
    const float* b2  = (const float*)d_in[12];
    const float* g2  = (const float*)d_in[13];
    const float* be2 = (const float*)d_in[14];
    const float* rm2 = (const float*)d_in[15];
    const float* rv2 = (const float*)d_in[16];
    const float* W3l = (const float*)d_in[17];
    const float* W3r = (const float*)d_in[18];
    const float* b3  = (const float*)d_in[19];
    float* out = (float*)d_out;
    int E = in_sizes[1];

    float *p_agg, *p_h1, *p_h2, *p_agg3, *p_r3;
    __half *p_xh, *p_h1h, *p_t3h;
    cudaGetSymbolAddress((void**)&p_agg,  g_agg);
    cudaGetSymbolAddress((void**)&p_h1,   g_h1);
    cudaGetSymbolAddress((void**)&p_h2,   g_h2);
    cudaGetSymbolAddress((void**)&p_agg3, g_agg3);
    cudaGetSymbolAddress((void**)&p_r3,   g_r3);
    cudaGetSymbolAddress((void**)&p_xh,   g_xh);
    cudaGetSymbolAddress((void**)&p_h1h,  g_h1h);
    cudaGetSymbolAddress((void**)&p_t3h,  g_t3h);

    cudaFuncSetAttribute(k_gemm_dual_bnrelu,
                         cudaFuncAttributeMaxDynamicSharedMemorySize, DSMEM);
    cudaFuncSetAttribute(k_gemm3,
                         cudaFuncAttributeMaxDynamicSharedMemorySize, DSMEM);

    // CSR build
    k_hist<<<(E + 255) / 256, 256>>>(dst, E);
    k_scan1<<<NBLK_SCAN, 1024>>>();
    k_scan2<<<1, 128>>>();
    k_scan3<<<(NN + 1 + 255) / 256, 256>>>(E);
    k_scatter<<<(E + 255) / 256, 256>>>(src, dst, E);

    // fp16 shadow of x
    k_x2h<<<(NN * 32 + 255) / 256, 256>>>(x, p_xh);

    const int gemm_blocks = (NN + 127) / 128;

    // layer 1
    k_aggr128h<<<NN / 8, 256>>>(p_xh, p_agg);
    k_gemm_dual_bnrelu<<<gemm_blocks, 256, DSMEM>>>(p_agg, W1l, x, W1r,
                                                    b1, g1, be1, rm1, rv1, p_h1, p_h1h);
    // layer 2
    k_aggr128h<<<NN / 8, 256>>>(p_h1h, p_agg);
    k_gemm_dual_bnrelu<<<gemm_blocks, 256, DSMEM>>>(p_agg, W2l, p_h1, W2r,
                                                    b2, g2, be2, rm2, rv2, p_h2, nullptr);
    // layer 3
    k_gemm3<<<gemm_blocks, 256, DSMEM>>>(p_h2, W3l, W3r, b3, p_t3h, p_r3);
    k_aggr64h<<<NN / 8, 256>>>(p_t3h, p_agg3);
    k_lsm_final<<<NN / 8, 256>>>(p_r3, p_agg3, out);
}

// round 7
// speedup vs baseline: 1.3045x; 1.3045x over previous
#include <cuda_runtime.h>
#include <cuda_bf16.h>
#include <cuda_fp16.h>
#include <math.h>
#include <stdint.h>

#define NN 100000
#define EE 1600000
#define NBLK_SCAN ((NN + 1023) / 1024)

// ---------------- device scratch (no allocations allowed) ----------------
__device__ int g_deg[NN];
__device__ int g_rowptr[NN + 1];
__device__ int g_fill[NN];
__device__ int g_csr[EE];
__device__ int g_blksum[NBLK_SCAN];

// bf16 (hi,lo) split pairs stored as packed bf16x2 words (64 words per 128-wide row)
__device__ unsigned g_xs_h[(size_t)NN * 64],  g_xs_l[(size_t)NN * 64];
__device__ unsigned g_agg_h[(size_t)NN * 64], g_agg_l[(size_t)NN * 64];
__device__ unsigned g_h1s_h[(size_t)NN * 64], g_h1s_l[(size_t)NN * 64];
__device__ unsigned g_h2s_h[(size_t)NN * 64], g_h2s_l[(size_t)NN * 64];
// weight splits: 128 rows x 64 words
__device__ unsigned g_w1lh[8192], g_w1ll[8192], g_w1rh[8192], g_w1rl[8192];
__device__ unsigned g_w2lh[8192], g_w2ll[8192], g_w2rh[8192], g_w2rl[8192];
__device__ unsigned g_w3ch[8192], g_w3cl[8192];   // combined [W3l;W3r]
// fp16 shadows for aggregation gathers
__device__ __half g_xh[(size_t)NN * 128];
__device__ __half g_h1h[(size_t)NN * 128];
__device__ __half g_t3h[(size_t)NN * 64];
__device__ float  g_agg3[(size_t)NN * 64];
__device__ float  g_r3[(size_t)NN * 64];

// ---------------- CSR construction ----------------
__global__ void k_hist(const int* __restrict__ dst, int E) {
    int e = blockIdx.x * blockDim.x + threadIdx.x;
    if (e < E) atomicAdd(&g_deg[dst[e]], 1);
}

__global__ void k_scan1() {
    __shared__ int s[1024];
    int i = threadIdx.x;
    int gid = blockIdx.x * 1024 + i;
    int v = (gid < NN) ? g_deg[gid] : 0;
    s[i] = v;
    __syncthreads();
    for (int off = 1; off < 1024; off <<= 1) {
        int add = (i >= off) ? s[i - off] : 0;
        __syncthreads();
        s[i] += add;
        __syncthreads();
    }
    if (gid < NN) g_rowptr[gid] = s[i] - v;
    if (i == 1023) g_blksum[blockIdx.x] = s[1023];
}

__global__ void k_scan2() {
    __shared__ int s[128];
    int i = threadIdx.x;
    int v = (i < NBLK_SCAN) ? g_blksum[i] : 0;
    s[i] = v;
    __syncthreads();
    for (int off = 1; off < 128; off <<= 1) {
        int a = (i >= off) ? s[i - off] : 0;
        __syncthreads();
        s[i] += a;
        __syncthreads();
    }
    if (i < NBLK_SCAN) g_blksum[i] = s[i] - v;
}

__global__ void k_scan3(int E) {
    int gid = blockIdx.x * blockDim.x + threadIdx.x;
    if (gid < NN) {
        int rp = g_rowptr[gid] + g_blksum[gid >> 10];
        g_rowptr[gid] = rp;
        g_fill[gid] = rp;
        g_deg[gid] = 0;   // pre-zero for the NEXT call
    } else if (gid == NN) {
        g_rowptr[NN] = E;
    }
}

__global__ void k_scatter(const int* __restrict__ src, const int* __restrict__ dst, int E) {
    int e = blockIdx.x * blockDim.x + threadIdx.x;
    if (e < E) {
        int p = atomicAdd(&g_fill[dst[e]], 1);
        g_csr[p] = src[e];
    }
}

// ---------------- bf16 split ----------------
__device__ __forceinline__ void bfsplit2(float v0, float v1, unsigned& hi, unsigned& lo) {
    __nv_bfloat16 h0 = __float2bfloat16(v0);
    __nv_bfloat16 h1 = __float2bfloat16(v1);
    float r0 = v0 - __bfloat162float(h0);
    float r1 = v1 - __bfloat162float(h1);
    __nv_bfloat16 l0 = __float2bfloat16(r0);
    __nv_bfloat16 l1 = __float2bfloat16(r1);
    hi = ((unsigned)__bfloat16_as_ushort(h1) << 16) | (unsigned)__bfloat16_as_ushort(h0);
    lo = ((unsigned)__bfloat16_as_ushort(l1) << 16) | (unsigned)__bfloat16_as_ushort(l0);
}

// ---------------- prep: weights -> split pairs ----------------
__global__ void k_wsplit(const float* __restrict__ W1l, const float* __restrict__ W1r,
                         const float* __restrict__ W2l, const float* __restrict__ W2r,
                         const float* __restrict__ W3l, const float* __restrict__ W3r) {
    int id = blockIdx.x * blockDim.x + threadIdx.x;   // 5 * 8192 words
    if (id >= 5 * 8192) return;
    int tile = id >> 13, rem = id & 8191;
    int row = rem >> 6, wp = rem & 63;
    const float* srcs[5] = {W1l, W1r, W2l, W2r, nullptr};
    const float* p;
    if (tile < 4) p = srcs[tile] + (size_t)row * 128 + wp * 2;
    else p = (row < 64) ? (W3l + (size_t)row * 128 + wp * 2)
                        : (W3r + (size_t)(row - 64) * 128 + wp * 2);
    float2 v = *(const float2*)p;
    unsigned hi, lo;
    bfsplit2(v.x, v.y, hi, lo);
    unsigned* dh[5] = {g_w1lh, g_w1rh, g_w2lh, g_w2rh, g_w3ch};
    unsigned* dl[5] = {g_w1ll, g_w1rl, g_w2ll, g_w2rl, g_w3cl};
    dh[tile][rem] = hi;
    dl[tile][rem] = lo;
}

// ---------------- prep: x -> fp16 shadow + split pair ----------------
__global__ void k_xprep(const float* __restrict__ x) {
    int i = blockIdx.x * blockDim.x + threadIdx.x;   // one float4 each
    if (i >= NN * 32) return;
    float4 v = ((const float4*)x)[i];
    __half2* o = (__half2*)g_xh + 2 * i;
    o[0] = __float22half2_rn(make_float2(v.x, v.y));
    o[1] = __float22half2_rn(make_float2(v.z, v.w));
    unsigned h0, l0, h1, l1;
    bfsplit2(v.x, v.y, h0, l0);
    bfsplit2(v.z, v.w, h1, l1);
    *(uint2*)(g_xs_h + 2 * (size_t)i) = make_uint2(h0, h1);
    *(uint2*)(g_xs_l + 2 * (size_t)i) = make_uint2(l0, l1);
}

// ---------------- mean aggregation (fp16 gather) -> split pair output ----------------
__device__ __forceinline__ void acc_h4(uint2 u, float* acc) {
    float2 f0 = __half22float2(*(__half2*)&u.x);
    float2 f1 = __half22float2(*(__half2*)&u.y);
    acc[0] += f0.x; acc[1] += f0.y; acc[2] += f1.x; acc[3] += f1.y;
}

__global__ void k_aggr128h(const __half* __restrict__ xh,
                           unsigned* __restrict__ out_h, unsigned* __restrict__ out_l) {
    int wid = blockIdx.x * (blockDim.x >> 5) + (threadIdx.x >> 5);
    int lane = threadIdx.x & 31;
    if (wid >= NN) return;
    int beg = g_rowptr[wid], end = g_rowptr[wid + 1];
    const uint2* base = (const uint2*)xh;
    float acc[4] = {0.f, 0.f, 0.f, 0.f};
    int j = beg;
    for (; j + 3 < end; j += 4) {
        int s0 = g_csr[j], s1 = g_csr[j + 1], s2 = g_csr[j + 2], s3 = g_csr[j + 3];
        uint2 u0 = base[(size_t)s0 * 32 + lane];
        uint2 u1 = base[(size_t)s1 * 32 + lane];
        uint2 u2 = base[(size_t)s2 * 32 + lane];
        uint2 u3 = base[(size_t)s3 * 32 + lane];
        acc_h4(u0, acc); acc_h4(u1, acc); acc_h4(u2, acc); acc_h4(u3, acc);
    }
    for (; j < end; j++) {
        uint2 u0 = base[(size_t)g_csr[j] * 32 + lane];
        acc_h4(u0, acc);
    }
    float inv = 1.f / fmaxf((float)(end - beg), 1.f);
    unsigned h0, l0, h1, l1;
    bfsplit2(acc[0] * inv, acc[1] * inv, h0, l0);
    bfsplit2(acc[2] * inv, acc[3] * inv, h1, l1);
    *(uint2*)(out_h + (size_t)wid * 64 + lane * 2) = make_uint2(h0, h1);
    *(uint2*)(out_l + (size_t)wid * 64 + lane * 2) = make_uint2(l0, l1);
}

__global__ void k_aggr64h(const __half* __restrict__ xh, float* __restrict__ out) {
    int wid = blockIdx.x * (blockDim.x >> 5) + (threadIdx.x >> 5);
    int lane = threadIdx.x & 31;
    if (wid >= NN) return;
    int beg = g_rowptr[wid], end = g_rowptr[wid + 1];
    const unsigned* base = (const unsigned*)xh;
    float a0 = 0.f, a1 = 0.f;
    int j = beg;
    for (; j + 3 < end; j += 4) {
        int s0 = g_csr[j], s1 = g_csr[j + 1], s2 = g_csr[j + 2], s3 = g_csr[j + 3];
        unsigned u0 = base[(size_t)s0 * 32 + lane];
        unsigned u1 = base[(size_t)s1 * 32 + lane];
        unsigned u2 = base[(size_t)s2 * 32 + lane];
        unsigned u3 = base[(size_t)s3 * 32 + lane];
        float2 f0 = __half22float2(*(__half2*)&u0);
        float2 f1 = __half22float2(*(__half2*)&u1);
        float2 f2 = __half22float2(*(__half2*)&u2);
        float2 f3 = __half22float2(*(__half2*)&u3);
        a0 += (f0.x + f1.x) + (f2.x + f3.x);
        a1 += (f0.y + f1.y) + (f2.y + f3.y);
    }
    for (; j < end; j++) {
        unsigned u0 = base[(size_t)g_csr[j] * 32 + lane];
        float2 f0 = __half22float2(*(__half2*)&u0);
        a0 += f0.x; a1 += f0.y;
    }
    float inv = 1.f / fmaxf((float)(end - beg), 1.f);
    *(float2*)(out + (size_t)wid * 64 + lane * 2) = make_float2(a0 * inv, a1 * inv);
}

// ---------------- GEMM machinery: cp.async pipeline + bf16 MMA ----------------
#define MMA_BF16(C, A, b0, b1)                                                \
    asm volatile(                                                             \
        "mma.sync.aligned.m16n8k16.row.col.f32.bf16.bf16.f32 "                \
        "{%0,%1,%2,%3},{%4,%5,%6,%7},{%8,%9},{%0,%1,%2,%3};"                  \
        : "+f"((C)[0]), "+f"((C)[1]), "+f"((C)[2]), "+f"((C)[3])              \
        : "r"((A)[0]), "r"((A)[1]), "r"((A)[2]), "r"((A)[3]),                 \
          "r"(b0), "r"(b1))

__device__ __forceinline__ uint32_t su32(const void* p) {
    uint32_t a;
    asm("{ .reg .u64 t; cvta.to.shared.u64 t, %1; cvt.u32.u64 %0, t; }" : "=r"(a) : "l"(p));
    return a;
}

// swizzle: XOR 16B-chunk index (bits 4:5) with row bits 1:2 -> conflict-free reads
#define SWZB(o) ((o) ^ (((o) >> 3) & 0x30))
#define STAGE_B 32768     // 4 tensors x 128 rows x 64B (32 bf16, K-chunk 32)
#define STAGES 3
#define DSMEM (STAGES * STAGE_B + 128)

// stage one K-chunk (32 wide) of A(hi,lo) + W(hi,lo) via cp.async (8x16B per thread)
__device__ __forceinline__ void issue_chunk(uint32_t sbase,
    const unsigned* __restrict__ Ah, const unsigned* __restrict__ Al,
    const unsigned* __restrict__ Wh, const unsigned* __restrict__ Wl,
    int k0w, int row0, int t)
{
#pragma unroll
    for (int tn = 0; tn < 4; tn++) {
#pragma unroll
        for (int j = 0; j < 2; j++) {
            int idx = t + j * 256;
            int row = idx >> 2, c16 = idx & 3;
            uint32_t dst = sbase + tn * 8192 + SWZB(row * 64 + c16 * 16);
            const unsigned* bp;
            int sz = 16;
            if (tn < 2) {
                int gr = row0 + row;
                if (gr >= NN) { sz = 0; gr = NN - 1; }
                bp = (tn == 0 ? Ah : Al) + (size_t)gr * 64 + k0w + c16 * 4;
            } else {
                bp = (tn == 2 ? Wh : Wl) + (size_t)row * 64 + k0w + c16 * 4;
            }
            asm volatile("cp.async.cg.shared.global [%0], [%1], 16, %2;"
                         :: "r"(dst), "l"(bp), "r"(sz) : "memory");
        }
    }
    asm volatile("cp.async.commit_group;" ::: "memory");
}

// MMA sweep over one staged chunk: 2 ksteps x 8nt x 2mt x 3 terms
__device__ __forceinline__ void mma_chunk(const char* sm, float c[2][8][4],
                                          int wr, int wc, int g, int tg)
{
    const char* Ah = sm;
    const char* Al = sm + 8192;
    const char* Wh = sm + 16384;
    const char* Wl = sm + 24576;
#pragma unroll
    for (int ks = 0; ks < 2; ks++) {
        const int kw = ks * 8;
        unsigned ahi[2][4], alo[2][4];
#pragma unroll
        for (int mt = 0; mt < 2; mt++) {
            int r = wr * 32 + mt * 16 + g;
            int o0 = SWZB(r * 64 + (kw + tg) * 4);
            int o1 = SWZB((r + 8) * 64 + (kw + tg) * 4);
            int o2 = SWZB(r * 64 + (kw + tg + 4) * 4);
            int o3 = SWZB((r + 8) * 64 + (kw + tg + 4) * 4);
            ahi[mt][0] = *(const unsigned*)(Ah + o0);
            ahi[mt][1] = *(const unsigned*)(Ah + o1);
            ahi[mt][2] = *(const unsigned*)(Ah + o2);
            ahi[mt][3] = *(const unsigned*)(Ah + o3);
            alo[mt][0] = *(const unsigned*)(Al + o0);
            alo[mt][1] = *(const unsigned*)(Al + o1);
            alo[mt][2] = *(const unsigned*)(Al + o2);
            alo[mt][3] = *(const unsigned*)(Al + o3);
        }
#pragma unroll
        for (int nt = 0; nt < 8; nt++) {
            int n = wc * 64 + nt * 8 + g;
            int p0 = SWZB(n * 64 + (kw + tg) * 4);
            int p1 = SWZB(n * 64 + (kw + tg + 4) * 4);
            unsigned bh0 = *(const unsigned*)(Wh + p0);
            unsigned bh1 = *(const unsigned*)(Wh + p1);
            unsigned bl0 = *(const unsigned*)(Wl + p0);
            unsigned bl1 = *(const unsigned*)(Wl + p1);
#pragma unroll
            for (int mt = 0; mt < 2; mt++) {
                MMA_BF16(c[mt][nt], ahi[mt], bh0, bh1);
                MMA_BF16(c[mt][nt], ahi[mt], bl0, bl1);
                MMA_BF16(c[mt][nt], alo[mt], bh0, bh1);
            }
        }
    }
}

// ---------------- dual GEMM + BN + ReLU, pipelined ----------------
// 8 chunks: cc<4 -> (A0,W0), cc>=4 -> (A1,W1); out written as split pair + optional fp16
__global__ __launch_bounds__(256, 2) void k_gemm_dual(
    const unsigned* __restrict__ A0h, const unsigned* __restrict__ A0l,
    const unsigned* __restrict__ W0h, const unsigned* __restrict__ W0l,
    const unsigned* __restrict__ A1h, const unsigned* __restrict__ A1l,
    const unsigned* __restrict__ W1h, const unsigned* __restrict__ W1l,
    const float* __restrict__ bias, const float* __restrict__ gamma,
    const float* __restrict__ beta, const float* __restrict__ rmean,
    const float* __restrict__ rvar,
    __half* __restrict__ out16, unsigned* __restrict__ outh,
    unsigned* __restrict__ outl)
{
    extern __shared__ uint4 dyn4[];
    __shared__ float s_sc[128], s_sh[128];
    const int t = threadIdx.x;
    const int lane = t & 31, wid = t >> 5;
    const int wr = wid & 3, wc = wid >> 2;
    const int g = lane >> 2, tg = lane & 3;
    const int row0 = blockIdx.x * 128;

    uint32_t sb0 = su32(dyn4);
    uint32_t ab = (sb0 + 127u) & ~127u;
    const char* smbase = (const char*)dyn4 + (ab - sb0);

    if (t < 128) {
        float s = gamma[t] * rsqrtf(rvar[t] + 1e-5f);
        s_sc[t] = s;
        s_sh[t] = beta[t] + (bias[t] - rmean[t]) * s;
    }

    float c[2][8][4];
#pragma unroll
    for (int mt = 0; mt < 2; mt++)
#pragma unroll
        for (int nt = 0; nt < 8; nt++)
#pragma unroll
            for (int q = 0; q < 4; q++) c[mt][nt][q] = 0.f;

    // prologue: stage chunks 0..2
#pragma unroll
    for (int s = 0; s < STAGES; s++) {
        int pass = s >> 2;
        issue_chunk(ab + s * STAGE_B,
                    pass ? A1h : A0h, pass ? A1l : A0l,
                    pass ? W1h : W0h, pass ? W1l : W0l,
                    (s & 3) * 16, row0, t);
    }

#pragma unroll
    for (int cc = 0; cc < 8; cc++) {
        asm volatile("cp.async.wait_group 2;" ::: "memory");
        __syncthreads();
        mma_chunk(smbase + (cc % 3) * STAGE_B, c, wr, wc, g, tg);
        __syncthreads();
        if (cc + STAGES < 8) {
            int nc = cc + STAGES;
            int pass = nc >> 2;
            issue_chunk(ab + (nc % 3) * STAGE_B,
                        pass ? A1h : A0h, pass ? A1l : A0l,
                        pass ? W1h : W0h, pass ? W1l : W0l,
                        (nc & 3) * 16, row0, t);
        } else {
            asm volatile("cp.async.commit_group;" ::: "memory");
        }
    }

    // epilogue: BN + ReLU -> split pair (+ fp16 shadow)
#pragma unroll
    for (int mt = 0; mt < 2; mt++) {
#pragma unroll
        for (int i = 0; i < 2; i++) {
            int r = row0 + wr * 32 + mt * 16 + g + i * 8;
            if (r >= NN) continue;
#pragma unroll
            for (int nt = 0; nt < 8; nt++) {
                int col = wc * 64 + nt * 8 + 2 * tg;
                float v0 = c[mt][nt][2 * i];
                float v1 = c[mt][nt][2 * i + 1];
                v0 = fmaxf(v0 * s_sc[col] + s_sh[col], 0.f);
                v1 = fmaxf(v1 * s_sc[col + 1] + s_sh[col + 1], 0.f);
                unsigned hh, ll;
                bfsplit2(v0, v1, hh, ll);
                outh[(size_t)r * 64 + (col >> 1)] = hh;
                outl[(size_t)r * 64 + (col >> 1)] = ll;
                if (out16)
                    *(__half2*)(out16 + (size_t)r * 128 + col) =
                        __float22half2_rn(make_float2(v0, v1));
            }
        }
    }
}

// ---------------- layer-3 GEMM (combined W), pipelined ----------------
__global__ __launch_bounds__(256, 2) void k_gemm3(
    const unsigned* __restrict__ Ah, const unsigned* __restrict__ Al,
    const float* __restrict__ bias,
    __half* __restrict__ t3h, float* __restrict__ r3)
{
    extern __shared__ uint4 dyn4[];
    const int t = threadIdx.x;
    const int lane = t & 31, wid = t >> 5;
    const int wr = wid & 3, wc = wid >> 2;
    const int g = lane >> 2, tg = lane & 3;
    const int row0 = blockIdx.x * 128;

    uint32_t sb0 = su32(dyn4);
    uint32_t ab = (sb0 + 127u) & ~127u;
    const char* smbase = (const char*)dyn4 + (ab - sb0);

    float c[2][8][4];
#pragma unroll
    for (int mt = 0; mt < 2; mt++)
#pragma unroll
        for (int nt = 0; nt < 8; nt++)
#pragma unroll
            for (int q = 0; q < 4; q++) c[mt][nt][q] = 0.f;

#pragma unroll
    for (int s = 0; s < STAGES; s++)
        issue_chunk(ab + s * STAGE_B, Ah, Al, g_w3ch, g_w3cl, s * 16, row0, t);

#pragma unroll
    for (int cc = 0; cc < 4; cc++) {
        asm volatile("cp.async.wait_group 2;" ::: "memory");
        __syncthreads();
        mma_chunk(smbase + (cc % 3) * STAGE_B, c, wr, wc, g, tg);
        __syncthreads();
        if (cc + STAGES < 4) {
            int nc = cc + STAGES;
            issue_chunk(ab + (nc % 3) * STAGE_B, Ah, Al, g_w3ch, g_w3cl,
                        nc * 16, row0, t);
        } else {
            asm volatile("cp.async.commit_group;" ::: "memory");
        }
    }

#pragma unroll
    for (int mt = 0; mt < 2; mt++) {
#pragma unroll
        for (int i = 0; i < 2; i++) {
            int r = row0 + wr * 32 + mt * 16 + g + i * 8;
            if (r >= NN) continue;
#pragma unroll
            for (int nt = 0; nt < 8; nt++) {
                int col = wc * 64 + nt * 8 + 2 * tg;   // 0..127
                float v0 = c[mt][nt][2 * i];
                float v1 = c[mt][nt][2 * i + 1];
                if (col < 64) {
                    *(__half2*)(t3h + (size_t)r * 64 + col) =
                        __float22half2_rn(make_float2(v0, v1));
                } else {
                    int cc2 = col - 64;
                    v0 += bias[cc2]; v1 += bias[cc2 + 1];
                    *(float2*)(r3 + (size_t)r * 64 + cc2) = make_float2(v0, v1);
                }
            }
        }
    }
}

// ---------------- final: add + log_softmax over 64 (warp per row) ----------------
__global__ void k_lsm_final(const float* __restrict__ r3, const float* __restrict__ agg3,
                            float* __restrict__ out) {
    int wid = blockIdx.x * (blockDim.x >> 5) + (threadIdx.x >> 5);
    int lane = threadIdx.x & 31;
    if (wid >= NN) return;
    float v0 = r3[(size_t)wid * 64 + lane] + agg3[(size_t)wid * 64 + lane];
    float v1 = r3[(size_t)wid * 64 + 32 + lane] + agg3[(size_t)wid * 64 + 32 + lane];
    float m = fmaxf(v0, v1);
#pragma unroll
    for (int o = 16; o > 0; o >>= 1) m = fmaxf(m, __shfl_xor_sync(0xffffffffu, m, o));
    float s = expf(v0 - m) + expf(v1 - m);
#pragma unroll
    for (int o = 16; o > 0; o >>= 1) s += __shfl_xor_sync(0xffffffffu, s, o);
    float l = m + logf(s);
    out[(size_t)wid * 64 + lane] = v0 - l;
    out[(size_t)wid * 64 + 32 + lane] = v1 - l;
}

// ---------------- launch ----------------
extern "C" void kernel_launch(void* const* d_in, const int* in_sizes, int n_in,
                              void* d_out, int out_size) {
    const float* x   = (const float*)d_in[0];
    const int*   src = (const int*)d_in[1];
    const int*   dst = (const int*)d_in[2];
    const float* W1l = (const float*)d_in[3];
    const float* W1r = (const float*)d_in[4];
    const float* b1  = (const float*)d_in[5];
    const float* g1  = (const float*)d_in[6];
    const float* be1 = (const float*)d_in[7];
    const float* rm1 = (const float*)d_in[8];
    const float* rv1 = (const float*)d_in[9];
    const float* W2l = (const float*)d_in[10];
    const float* W2r = (const float*)d_in[11];
    const float* b2  = (const float*)d_in[12];
    const float* g2  = (const float*)d_in[13];
    const float* be2 = (const float*)d_in[14];
    const float* rm2 = (const float*)d_in[15];
    const float* rv2 = (const float*)d_in[16];
    const float* W3l = (const float*)d_in[17];
    const float* W3r = (const float*)d_in[18];
    const float* b3  = (const float*)d_in[19];
    float* out = (float*)d_out;
    int E = in_sizes[1];

    unsigned *p_xsh, *p_xsl, *p_aggh, *p_aggl, *p_h1sh, *p_h1sl, *p_h2sh, *p_h2sl;
    __half *p_xh, *p_h1h, *p_t3h;
    float *p_agg3, *p_r3;
    cudaGetSymbolAddress((void**)&p_xsh,  g_xs_h);
    cudaGetSymbolAddress((void**)&p_xsl,  g_xs_l);
    cudaGetSymbolAddress((void**)&p_aggh, g_agg_h);
    cudaGetSymbolAddress((void**)&p_aggl, g_agg_l);
    cudaGetSymbolAddress((void**)&p_h1sh, g_h1s_h);
    cudaGetSymbolAddress((void**)&p_h1sl, g_h1s_l);
    cudaGetSymbolAddress((void**)&p_h2sh, g_h2s_h);
    cudaGetSymbolAddress((void**)&p_h2sl, g_h2s_l);
    cudaGetSymbolAddress((void**)&p_xh,   g_xh);
    cudaGetSymbolAddress((void**)&p_h1h,  g_h1h);
    cudaGetSymbolAddress((void**)&p_t3h,  g_t3h);
    cudaGetSymbolAddress((void**)&p_agg3, g_agg3);
    cudaGetSymbolAddress((void**)&p_r3,   g_r3);

    unsigned *p_w1lh, *p_w1ll, *p_w1rh, *p_w1rl, *p_w2lh, *p_w2ll, *p_w2rh, *p_w2rl;
    cudaGetSymbolAddress((void**)&p_w1lh, g_w1lh);
    cudaGetSymbolAddress((void**)&p_w1ll, g_w1ll);
    cudaGetSymbolAddress((void**)&p_w1rh, g_w1rh);
    cudaGetSymbolAddress((void**)&p_w1rl, g_w1rl);
    cudaGetSymbolAddress((void**)&p_w2lh, g_w2lh);
    cudaGetSymbolAddress((void**)&p_w2ll, g_w2ll);
    cudaGetSymbolAddress((void**)&p_w2rh, g_w2rh);
    cudaGetSymbolAddress((void**)&p_w2rl, g_w2rl);

    cudaFuncSetAttribute(k_gemm_dual,
                         cudaFuncAttributeMaxDynamicSharedMemorySize, DSMEM);
    cudaFuncSetAttribute(k_gemm3,
                         cudaFuncAttributeMaxDynamicSharedMemorySize, DSMEM);

    // CSR build
    k_hist<<<(E + 255) / 256, 256>>>(dst, E);
    k_scan1<<<NBLK_SCAN, 1024>>>();
    k_scan2<<<1, 128>>>();
    k_scan3<<<(NN + 1 + 255) / 256, 256>>>(E);
    k_scatter<<<(E + 255) / 256, 256>>>(src, dst, E);

    // one-time splits
    k_wsplit<<<(5 * 8192 + 255) / 256, 256>>>(W1l, W1r, W2l, W2r, W3l, W3r);
    k_xprep<<<(NN * 32 + 255) / 256, 256>>>(x);

    const int gemm_blocks = (NN + 127) / 128;

    // layer 1
    k_aggr128h<<<NN / 8, 256>>>(p_xh, p_aggh, p_aggl);
    k_gemm_dual<<<gemm_blocks, 256, DSMEM>>>(p_aggh, p_aggl, p_w1lh, p_w1ll,
                                             p_xsh, p_xsl, p_w1rh, p_w1rl,
                                             b1, g1, be1, rm1, rv1,
                                             p_h1h, p_h1sh, p_h1sl);
    // layer 2
    k_aggr128h<<<NN / 8, 256>>>(p_h1h, p_aggh, p_aggl);
    k_gemm_dual<<<gemm_blocks, 256, DSMEM>>>(p_aggh, p_aggl, p_w2lh, p_w2ll,
                                             p_h1sh, p_h1sl, p_w2rh, p_w2rl,
                                             b2, g2, be2, rm2, rv2,
                                             nullptr, p_h2sh, p_h2sl);
    // layer 3
    k_gemm3<<<gemm_blocks, 256, DSMEM>>>(p_h2sh, p_h2sl, b3, p_t3h, p_r3);
    k_aggr64h<<<NN / 8, 256>>>(p_t3h, p_agg3);
    k_lsm_final<<<NN / 8, 256>>>(p_r3, p_agg3, out);
}

// round 8
// speedup vs baseline: 1.9557x; 1.4992x over previous
#include <cuda_runtime.h>
#include <cuda_fp16.h>
#include <math.h>
#include <stdint.h>

#define NN 100000
#define EE 1600000
#define NBLK_SCAN ((NN + 1023) / 1024)

// ---------------- device scratch (no allocations allowed) ----------------
__device__ int g_deg[NN];
__device__ int g_rowptr[NN + 1];
__device__ int g_fill[NN];
__device__ int g_csr[EE];
__device__ int g_blksum[NBLK_SCAN];

// fp16 activations (single copy serves gathers AND GEMM A-operands)
__device__ __half g_xh[(size_t)NN * 128];
__device__ __half g_aggh[(size_t)NN * 128];
__device__ __half g_h1h[(size_t)NN * 128];
__device__ __half g_h2h[(size_t)NN * 128];
__device__ __half g_t3h[(size_t)NN * 64];
__device__ float  g_agg3[(size_t)NN * 64];
__device__ float  g_r3[(size_t)NN * 64];
// fp16 weights (packed half2 words), w3c = combined [W3l;W3r]
__device__ unsigned g_w1l[8192], g_w1r[8192], g_w2l[8192], g_w2r[8192], g_w3c[8192];

// ---------------- CSR construction ----------------
__global__ void k_hist(const int* __restrict__ dst, int E) {
    int e = blockIdx.x * blockDim.x + threadIdx.x;
    if (e < E) atomicAdd(&g_deg[dst[e]], 1);
}

__global__ void k_scan1() {
    __shared__ int s[1024];
    int i = threadIdx.x;
    int gid = blockIdx.x * 1024 + i;
    int v = (gid < NN) ? g_deg[gid] : 0;
    s[i] = v;
    __syncthreads();
    for (int off = 1; off < 1024; off <<= 1) {
        int add = (i >= off) ? s[i - off] : 0;
        __syncthreads();
        s[i] += add;
        __syncthreads();
    }
    if (gid < NN) g_rowptr[gid] = s[i] - v;
    if (i == 1023) g_blksum[blockIdx.x] = s[1023];
}

__global__ void k_scan2() {
    __shared__ int s[128];
    int i = threadIdx.x;
    int v = (i < NBLK_SCAN) ? g_blksum[i] : 0;
    s[i] = v;
    __syncthreads();
    for (int off = 1; off < 128; off <<= 1) {
        int a = (i >= off) ? s[i - off] : 0;
        __syncthreads();
        s[i] += a;
        __syncthreads();
    }
    if (i < NBLK_SCAN) g_blksum[i] = s[i] - v;
}

__global__ void k_scan3(int E) {
    int gid = blockIdx.x * blockDim.x + threadIdx.x;
    if (gid < NN) {
        int rp = g_rowptr[gid] + g_blksum[gid >> 10];
        g_rowptr[gid] = rp;
        g_fill[gid] = rp;
        g_deg[gid] = 0;   // pre-zero for the NEXT call (module-load state is also 0)
    } else if (gid == NN) {
        g_rowptr[NN] = E;
    }
}

__global__ void k_scatter(const int* __restrict__ src, const int* __restrict__ dst, int E) {
    int e = blockIdx.x * blockDim.x + threadIdx.x;
    if (e < E) {
        int p = atomicAdd(&g_fill[dst[e]], 1);
        g_csr[p] = src[e];
    }
}

// ---------------- prep: weights -> fp16 ----------------
__global__ void k_wprep(const float* __restrict__ W1l, const float* __restrict__ W1r,
                        const float* __restrict__ W2l, const float* __restrict__ W2r,
                        const float* __restrict__ W3l, const float* __restrict__ W3r) {
    int id = blockIdx.x * blockDim.x + threadIdx.x;   // 5 * 8192 half2 words
    if (id >= 5 * 8192) return;
    int tile = id >> 13, rem = id & 8191;
    int row = rem >> 6, wp = rem & 63;
    const float* srcs[4] = {W1l, W1r, W2l, W2r};
    const float* p;
    if (tile < 4) p = srcs[tile] + (size_t)row * 128 + wp * 2;
    else p = (row < 64) ? (W3l + (size_t)row * 128 + wp * 2)
                        : (W3r + (size_t)(row - 64) * 128 + wp * 2);
    float2 v = *(const float2*)p;
    __half2 h = __float22half2_rn(v);
    unsigned* dsts[5] = {g_w1l, g_w1r, g_w2l, g_w2r, g_w3c};
    dsts[tile][rem] = *(unsigned*)&h;
}

// ---------------- prep: x -> fp16 ----------------
__global__ void k_xprep(const float* __restrict__ x) {
    int i = blockIdx.x * blockDim.x + threadIdx.x;   // one float4 each
    if (i >= NN * 32) return;
    float4 v = ((const float4*)x)[i];
    __half2* o = (__half2*)g_xh + 2 * i;
    o[0] = __float22half2_rn(make_float2(v.x, v.y));
    o[1] = __float22half2_rn(make_float2(v.z, v.w));
}

// ---------------- mean aggregation over fp16 rows (warp per node) ----------------
__device__ __forceinline__ void acc_h4(uint2 u, float* acc) {
    float2 f0 = __half22float2(*(__half2*)&u.x);
    float2 f1 = __half22float2(*(__half2*)&u.y);
    acc[0] += f0.x; acc[1] += f0.y; acc[2] += f1.x; acc[3] += f1.y;
}

__global__ void k_aggr128h(const __half* __restrict__ xh, __half* __restrict__ outh) {
    int wid = blockIdx.x * (blockDim.x >> 5) + (threadIdx.x >> 5);
    int lane = threadIdx.x & 31;
    if (wid >= NN) return;
    int beg = g_rowptr[wid], end = g_rowptr[wid + 1];
    const uint2* base = (const uint2*)xh;
    float acc[4] = {0.f, 0.f, 0.f, 0.f};
    int j = beg;
    for (; j + 3 < end; j += 4) {
        int s0 = g_csr[j], s1 = g_csr[j + 1], s2 = g_csr[j + 2], s3 = g_csr[j + 3];
        uint2 u0 = base[(size_t)s0 * 32 + lane];
        uint2 u1 = base[(size_t)s1 * 32 + lane];
        uint2 u2 = base[(size_t)s2 * 32 + lane];
        uint2 u3 = base[(size_t)s3 * 32 + lane];
        acc_h4(u0, acc); acc_h4(u1, acc); acc_h4(u2, acc); acc_h4(u3, acc);
    }
    for (; j < end; j++) {
        uint2 u0 = base[(size_t)g_csr[j] * 32 + lane];
        acc_h4(u0, acc);
    }
    float inv = 1.f / fmaxf((float)(end - beg), 1.f);
    __half2 h0 = __float22half2_rn(make_float2(acc[0] * inv, acc[1] * inv));
    __half2 h1 = __float22half2_rn(make_float2(acc[2] * inv, acc[3] * inv));
    *(uint2*)(outh + (size_t)wid * 128 + lane * 4) =
        make_uint2(*(unsigned*)&h0, *(unsigned*)&h1);
}

__global__ void k_aggr64h(const __half* __restrict__ xh, float* __restrict__ out) {
    int wid = blockIdx.x * (blockDim.x >> 5) + (threadIdx.x >> 5);
    int lane = threadIdx.x & 31;
    if (wid >= NN) return;
    int beg = g_rowptr[wid], end = g_rowptr[wid + 1];
    const unsigned* base = (const unsigned*)xh;
    float a0 = 0.f, a1 = 0.f;
    int j = beg;
    for (; j + 3 < end; j += 4) {
        int s0 = g_csr[j], s1 = g_csr[j + 1], s2 = g_csr[j + 2], s3 = g_csr[j + 3];
        unsigned u0 = base[(size_t)s0 * 32 + lane];
        unsigned u1 = base[(size_t)s1 * 32 + lane];
        unsigned u2 = base[(size_t)s2 * 32 + lane];
        unsigned u3 = base[(size_t)s3 * 32 + lane];
        float2 f0 = __half22float2(*(__half2*)&u0);
        float2 f1 = __half22float2(*(__half2*)&u1);
        float2 f2 = __half22float2(*(__half2*)&u2);
        float2 f3 = __half22float2(*(__half2*)&u3);
        a0 += (f0.x + f1.x) + (f2.x + f3.x);
        a1 += (f0.y + f1.y) + (f2.y + f3.y);
    }
    for (; j < end; j++) {
        unsigned u0 = base[(size_t)g_csr[j] * 32 + lane];
        float2 f0 = __half22float2(*(__half2*)&u0);
        a0 += f0.x; a1 += f0.y;
    }
    float inv = 1.f / fmaxf((float)(end - beg), 1.f);
    *(float2*)(out + (size_t)wid * 64 + lane * 2) = make_float2(a0 * inv, a1 * inv);
}

// ---------------- GEMM machinery: cp.async pipeline + fp16 MMA ----------------
#define MMA_F16(C, A, b0, b1)                                                 \
    asm volatile(                                                             \
        "mma.sync.aligned.m16n8k16.row.col.f32.f16.f16.f32 "                  \
        "{%0,%1,%2,%3},{%4,%5,%6,%7},{%8,%9},{%0,%1,%2,%3};"                  \
        : "+f"((C)[0]), "+f"((C)[1]), "+f"((C)[2]), "+f"((C)[3])              \
        : "r"((A)[0]), "r"((A)[1]), "r"((A)[2]), "r"((A)[3]),                 \
          "r"(b0), "r"(b1))

__device__ __forceinline__ uint32_t su32(const void* p) {
    uint32_t a;
    asm("{ .reg .u64 t; cvta.to.shared.u64 t, %1; cvt.u32.u64 %0, t; }" : "=r"(a) : "l"(p));
    return a;
}

// swizzle: XOR byte bits [4:5] with row bits [1:2] -> conflict-free frag reads
#define SWZB(o) ((o) ^ (((o) >> 3) & 0x30))
#define STAGE_B 16384     // 2 tensors x 128 rows x 64B (32 fp16, K-chunk 32)
#define STAGES 3
#define DSMEM (STAGES * STAGE_B + 128)

// stage one K-chunk of A (fp16) + W (fp16) via cp.async (4x16B per thread)
// k0w = word offset (rows are 64 half2 words = 128 fp16)
__device__ __forceinline__ void issue_chunk(uint32_t sbase,
    const unsigned* __restrict__ A, const unsigned* __restrict__ W,
    int k0w, int row0, int t)
{
#pragma unroll
    for (int tn = 0; tn < 2; tn++) {
#pragma unroll
        for (int j = 0; j < 2; j++) {
            int idx = t + j * 256;
            int row = idx >> 2, c16 = idx & 3;
            uint32_t dstp = sbase + tn * 8192 + SWZB(row * 64 + c16 * 16);
            const unsigned* bp;
            int sz = 16;
            if (tn == 0) {
                int gr = row0 + row;
                if (gr >= NN) { sz = 0; gr = NN - 1; }
                bp = A + (size_t)gr * 64 + k0w + c16 * 4;
            } else {
                bp = W + (size_t)row * 64 + k0w + c16 * 4;
            }
            asm volatile("cp.async.cg.shared.global [%0], [%1], 16, %2;"
                         :: "r"(dstp), "l"(bp), "r"(sz) : "memory");
        }
    }
    asm volatile("cp.async.commit_group;" ::: "memory");
}

// MMA sweep over one staged chunk: 2 ksteps x 8nt x 2mt (single term)
__device__ __forceinline__ void mma_chunk(const char* sm, float c[2][8][4],
                                          int wr, int wc, int g, int tg)
{
    const char* Am = sm;
    const char* Wm = sm + 8192;
#pragma unroll
    for (int ks = 0; ks < 2; ks++) {
        const int kw = ks * 8;
        unsigned a[2][4];
#pragma unroll
        for (int mt = 0; mt < 2; mt++) {
            int r = wr * 32 + mt * 16 + g;
            a[mt][0] = *(const unsigned*)(Am + SWZB(r * 64 + (kw + tg) * 4));
            a[mt][1] = *(const unsigned*)(Am + SWZB((r + 8) * 64 + (kw + tg) * 4));
            a[mt][2] = *(const unsigned*)(Am + SWZB(r * 64 + (kw + tg + 4) * 4));
            a[mt][3] = *(const unsigned*)(Am + SWZB((r + 8) * 64 + (kw + tg + 4) * 4));
        }
#pragma unroll
        for (int nt = 0; nt < 8; nt++) {
            int n = wc * 64 + nt * 8 + g;
            unsigned b0 = *(const unsigned*)(Wm + SWZB(n * 64 + (kw + tg) * 4));
            unsigned b1 = *(const unsigned*)(Wm + SWZB(n * 64 + (kw + tg + 4) * 4));
#pragma unroll
            for (int mt = 0; mt < 2; mt++)
                MMA_F16(c[mt][nt], a[mt], b0, b1);
        }
    }
}

// ---------------- dual GEMM + BN + ReLU, pipelined ----------------
// 8 chunks: cc<4 -> (A0,W0), cc>=4 -> (A1,W1); output fp16
__global__ __launch_bounds__(256, 2) void k_gemm_dual(
    const unsigned* __restrict__ A0, const unsigned* __restrict__ W0,
    const unsigned* __restrict__ A1, const unsigned* __restrict__ W1,
    const float* __restrict__ bias, const float* __restrict__ gamma,
    const float* __restrict__ beta, const float* __restrict__ rmean,
    const float* __restrict__ rvar, __half* __restrict__ outh)
{
    extern __shared__ uint4 dyn4[];
    __shared__ float s_sc[128], s_sh[128];
    const int t = threadIdx.x;
    const int lane = t & 31, wid = t >> 5;
    const int wr = wid & 3, wc = wid >> 2;
    const int g = lane >> 2, tg = lane & 3;
    const int row0 = blockIdx.x * 128;

    uint32_t sb0 = su32(dyn4);
    uint32_t ab = (sb0 + 127u) & ~127u;
    const char* smbase = (const char*)dyn4 + (ab - sb0);

    if (t < 128) {
        float s = gamma[t] * rsqrtf(rvar[t] + 1e-5f);
        s_sc[t] = s;
        s_sh[t] = beta[t] + (bias[t] - rmean[t]) * s;
    }

    float c[2][8][4];
#pragma unroll
    for (int mt = 0; mt < 2; mt++)
#pragma unroll
        for (int nt = 0; nt < 8; nt++)
#pragma unroll
            for (int q = 0; q < 4; q++) c[mt][nt][q] = 0.f;

#pragma unroll
    for (int s = 0; s < STAGES; s++)
        issue_chunk(ab + s * STAGE_B, A0, W0, s * 16, row0, t);

#pragma unroll
    for (int cc = 0; cc < 8; cc++) {
        asm volatile("cp.async.wait_group 2;" ::: "memory");
        __syncthreads();
        mma_chunk(smbase + (cc % 3) * STAGE_B, c, wr, wc, g, tg);
        __syncthreads();
        if (cc + STAGES < 8) {
            int nc = cc + STAGES;
            int pass = nc >> 2;
            issue_chunk(ab + (nc % 3) * STAGE_B,
                        pass ? A1 : A0, pass ? W1 : W0, (nc & 3) * 16, row0, t);
        } else {
            asm volatile("cp.async.commit_group;" ::: "memory");
        }
    }

    // epilogue: BN + ReLU -> fp16
#pragma unroll
    for (int mt = 0; mt < 2; mt++) {
#pragma unroll
        for (int i = 0; i < 2; i++) {
            int r = row0 + wr * 32 + mt * 16 + g + i * 8;
            if (r >= NN) continue;
#pragma unroll
            for (int nt = 0; nt < 8; nt++) {
                int col = wc * 64 + nt * 8 + 2 * tg;
                float v0 = c[mt][nt][2 * i];
                float v1 = c[mt][nt][2 * i + 1];
                v0 = fmaxf(v0 * s_sc[col] + s_sh[col], 0.f);
                v1 = fmaxf(v1 * s_sc[col + 1] + s_sh[col + 1], 0.f);
                *(__half2*)(outh + (size_t)r * 128 + col) =
                    __float22half2_rn(make_float2(v0, v1));
            }
        }
    }
}

// ---------------- layer-3 GEMM (combined W), pipelined ----------------
__global__ __launch_bounds__(256, 2) void k_gemm3(
    const unsigned* __restrict__ A, const unsigned* __restrict__ W,
    const float* __restrict__ bias,
    __half* __restrict__ t3h, float* __restrict__ r3)
{
    extern __shared__ uint4 dyn4[];
    const int t = threadIdx.x;
    const int lane = t & 31, wid = t >> 5;
    const int wr = wid & 3, wc = wid >> 2;
    const int g = lane >> 2, tg = lane & 3;
    const int row0 = blockIdx.x * 128;

    uint32_t sb0 = su32(dyn4);
    uint32_t ab = (sb0 + 127u) & ~127u;
    const char* smbase = (const char*)dyn4 + (ab - sb0);

    float c[2][8][4];
#pragma unroll
    for (int mt = 0; mt < 2; mt++)
#pragma unroll
        for (int nt = 0; nt < 8; nt++)
#pragma unroll
            for (int q = 0; q < 4; q++) c[mt][nt][q] = 0.f;

#pragma unroll
    for (int s = 0; s < STAGES; s++)
        issue_chunk(ab + s * STAGE_B, A, W, s * 16, row0, t);

#pragma unroll
    for (int cc = 0; cc < 4; cc++) {
        asm volatile("cp.async.wait_group 2;" ::: "memory");
        __syncthreads();
        mma_chunk(smbase + (cc % 3) * STAGE_B, c, wr, wc, g, tg);
        __syncthreads();
        if (cc + STAGES < 4) {
            int nc = cc + STAGES;
            issue_chunk(ab + (nc % 3) * STAGE_B, A, W, nc * 16, row0, t);
        } else {
            asm volatile("cp.async.commit_group;" ::: "memory");
        }
    }

#pragma unroll
    for (int mt = 0; mt < 2; mt++) {
#pragma unroll
        for (int i = 0; i < 2; i++) {
            int r = row0 + wr * 32 + mt * 16 + g + i * 8;
            if (r >= NN) continue;
#pragma unroll
            for (int nt = 0; nt < 8; nt++) {
                int col = wc * 64 + nt * 8 + 2 * tg;   // 0..127
                float v0 = c[mt][nt][2 * i];
                float v1 = c[mt][nt][2 * i + 1];
                if (col < 64) {
                    *(__half2*)(t3h + (size_t)r * 64 + col) =
                        __float22half2_rn(make_float2(v0, v1));
                } else {
                    int cc2 = col - 64;
                    v0 += bias[cc2]; v1 += bias[cc2 + 1];
                    *(float2*)(r3 + (size_t)r * 64 + cc2) = make_float2(v0, v1);
                }
            }
        }
    }
}

// ---------------- final: add + log_softmax over 64 (warp per row) ----------------
__global__ void k_lsm_final(const float* __restrict__ r3, const float* __restrict__ agg3,
                            float* __restrict__ out) {
    int wid = blockIdx.x * (blockDim.x >> 5) + (threadIdx.x >> 5);
    int lane = threadIdx.x & 31;
    if (wid >= NN) return;
    float v0 = r3[(size_t)wid * 64 + lane] + agg3[(size_t)wid * 64 + lane];
    float v1 = r3[(size_t)wid * 64 + 32 + lane] + agg3[(size_t)wid * 64 + 32 + lane];
    float m = fmaxf(v0, v1);
#pragma unroll
    for (int o = 16; o > 0; o >>= 1) m = fmaxf(m, __shfl_xor_sync(0xffffffffu, m, o));
    float s = expf(v0 - m) + expf(v1 - m);
#pragma unroll
    for (int o = 16; o > 0; o >>= 1) s += __shfl_xor_sync(0xffffffffu, s, o);
    float l = m + logf(s);
    out[(size_t)wid * 64 + lane] = v0 - l;
    out[(size_t)wid * 64 + 32 + lane] = v1 - l;
}

// ---------------- launch ----------------
extern "C" void kernel_launch(void* const* d_in, const int* in_sizes, int n_in,
                              void* d_out, int out_size) {
    const float* x   = (const float*)d_in[0];
    const int*   src = (const int*)d_in[1];
    const int*   dst = (const int*)d_in[2];
    const float* W1l = (const float*)d_in[3];
    const float* W1r = (const float*)d_in[4];
    const float* b1  = (const float*)d_in[5];
    const float* g1  = (const float*)d_in[6];
    const float* be1 = (const float*)d_in[7];
    const float* rm1 = (const float*)d_in[8];
    const float* rv1 = (const float*)d_in[9];
    const float* W2l = (const float*)d_in[10];
    const float* W2r = (const float*)d_in[11];
    const float* b2  = (const float*)d_in[12];
    const float* g2  = (const float*)d_in[13];
    const float* be2 = (const float*)d_in[14];
    const float* rm2 = (const float*)d_in[15];
    const float* rv2 = (const float*)d_in[16];
    const float* W3l = (const float*)d_in[17];
    const float* W3r = (const float*)d_in[18];
    const float* b3  = (const float*)d_in[19];
    float* out = (float*)d_out;
    int E = in_sizes[1];

    __half *p_xh, *p_aggh, *p_h1h, *p_h2h, *p_t3h;
    float *p_agg3, *p_r3;
    unsigned *p_w1l, *p_w1r, *p_w2l, *p_w2r, *p_w3c;
    cudaGetSymbolAddress((void**)&p_xh,   g_xh);
    cudaGetSymbolAddress((void**)&p_aggh, g_aggh);
    cudaGetSymbolAddress((void**)&p_h1h,  g_h1h);
    cudaGetSymbolAddress((void**)&p_h2h,  g_h2h);
    cudaGetSymbolAddress((void**)&p_t3h,  g_t3h);
    cudaGetSymbolAddress((void**)&p_agg3, g_agg3);
    cudaGetSymbolAddress((void**)&p_r3,   g_r3);
    cudaGetSymbolAddress((void**)&p_w1l,  g_w1l);
    cudaGetSymbolAddress((void**)&p_w1r,  g_w1r);
    cudaGetSymbolAddress((void**)&p_w2l,  g_w2l);
    cudaGetSymbolAddress((void**)&p_w2r,  g_w2r);
    cudaGetSymbolAddress((void**)&p_w3c,  g_w3c);

    cudaFuncSetAttribute(k_gemm_dual,
                         cudaFuncAttributeMaxDynamicSharedMemorySize, DSMEM);
    cudaFuncSetAttribute(k_gemm3,
                         cudaFuncAttributeMaxDynamicSharedMemorySize, DSMEM);

    // CSR build
    k_hist<<<(E + 255) / 256, 256>>>(dst, E);
    k_scan1<<<NBLK_SCAN, 1024>>>();
    k_scan2<<<1, 128>>>();
    k_scan3<<<(NN + 1 + 255) / 256, 256>>>(E);
    k_scatter<<<(E + 255) / 256, 256>>>(src, dst, E);

    // one-time fp16 prep
    k_wprep<<<(5 * 8192 + 255) / 256, 256>>>(W1l, W1r, W2l, W2r, W3l, W3r);
    k_xprep<<<(NN * 32 + 255) / 256, 256>>>(x);

    const int gemm_blocks = (NN + 127) / 128;

    // layer 1
    k_aggr128h<<<NN / 8, 256>>>(p_xh, p_aggh);
    k_gemm_dual<<<gemm_blocks, 256, DSMEM>>>(
        (const unsigned*)p_aggh, p_w1l, (const unsigned*)p_xh, p_w1r,
        b1, g1, be1, rm1, rv1, p_h1h);
    // layer 2
    k_aggr128h<<<NN / 8, 256>>>(p_h1h, p_aggh);
    k_gemm_dual<<<gemm_blocks, 256, DSMEM>>>(
        (const unsigned*)p_aggh, p_w2l, (const unsigned*)p_h1h, p_w2r,
        b2, g2, be2, rm2, rv2, p_h2h);
    // layer 3
    k_gemm3<<<gemm_blocks, 256, DSMEM>>>(
        (const unsigned*)p_h2h, p_w3c, b3, p_t3h, p_r3);
    k_aggr64h<<<NN / 8, 256>>>(p_t3h, p_agg3);
    k_lsm_final<<<NN / 8, 256>>>(p_r3, p_agg3, out);
}

// round 9
// speedup vs baseline: 2.1044x; 1.0761x over previous
#include <cuda_runtime.h>
#include <cuda_fp16.h>
#include <math.h>
#include <stdint.h>

#define NN 100000
#define EE 1600000
#define NBLK_SCAN ((NN + 1023) / 1024)

// ---------------- device scratch (no allocations allowed) ----------------
__device__ int g_deg[NN];
__device__ int g_rowptr[NN + 1];
__device__ int g_fill[NN];
__device__ int g_csr[EE];
__device__ int g_blksum[NBLK_SCAN];

// fp16 activations (single copy serves gathers AND GEMM A-operands)
__device__ __half g_xh[(size_t)NN * 128];
__device__ __half g_aggh[(size_t)NN * 128];
__device__ __half g_h1h[(size_t)NN * 128];
__device__ __half g_t3h[(size_t)NN * 64];
__device__ float  g_r3[(size_t)NN * 64];
// fp16 weights (packed half2 words), w3c = combined [W3l;W3r]
__device__ unsigned g_w1l[8192], g_w1r[8192], g_w2l[8192], g_w2r[8192], g_w3c[8192];

// ---------------- CSR construction ----------------
__global__ void k_hist(const int* __restrict__ dst, int E) {
    int e = blockIdx.x * blockDim.x + threadIdx.x;
    if (e < E) atomicAdd(&g_deg[dst[e]], 1);
}

__global__ void k_scan1() {
    __shared__ int s[1024];
    int i = threadIdx.x;
    int gid = blockIdx.x * 1024 + i;
    int v = (gid < NN) ? g_deg[gid] : 0;
    s[i] = v;
    __syncthreads();
    for (int off = 1; off < 1024; off <<= 1) {
        int add = (i >= off) ? s[i - off] : 0;
        __syncthreads();
        s[i] += add;
        __syncthreads();
    }
    if (gid < NN) g_rowptr[gid] = s[i] - v;
    if (i == 1023) g_blksum[blockIdx.x] = s[1023];
}

__global__ void k_scan2() {
    __shared__ int s[128];
    int i = threadIdx.x;
    int v = (i < NBLK_SCAN) ? g_blksum[i] : 0;
    s[i] = v;
    __syncthreads();
    for (int off = 1; off < 128; off <<= 1) {
        int a = (i >= off) ? s[i - off] : 0;
        __syncthreads();
        s[i] += a;
        __syncthreads();
    }
    if (i < NBLK_SCAN) g_blksum[i] = s[i] - v;
}

__global__ void k_scan3(int E) {
    int gid = blockIdx.x * blockDim.x + threadIdx.x;
    if (gid < NN) {
        int rp = g_rowptr[gid] + g_blksum[gid >> 10];
        g_rowptr[gid] = rp;
        g_fill[gid] = rp;
        g_deg[gid] = 0;   // pre-zero for the NEXT call (module-load state is also 0)
    } else if (gid == NN) {
        g_rowptr[NN] = E;
    }
}

__global__ void k_scatter(const int* __restrict__ src, const int* __restrict__ dst, int E) {
    int e = blockIdx.x * blockDim.x + threadIdx.x;
    if (e < E) {
        int p = atomicAdd(&g_fill[dst[e]], 1);
        g_csr[p] = src[e];
    }
}

// ---------------- prep: weights -> fp16 ----------------
__global__ void k_wprep(const float* __restrict__ W1l, const float* __restrict__ W1r,
                        const float* __restrict__ W2l, const float* __restrict__ W2r,
                        const float* __restrict__ W3l, const float* __restrict__ W3r) {
    int id = blockIdx.x * blockDim.x + threadIdx.x;   // 5 * 8192 half2 words
    if (id >= 5 * 8192) return;
    int tile = id >> 13, rem = id & 8191;
    int row = rem >> 6, wp = rem & 63;
    const float* srcs[4] = {W1l, W1r, W2l, W2r};
    const float* p;
    if (tile < 4) p = srcs[tile] + (size_t)row * 128 + wp * 2;
    else p = (row < 64) ? (W3l + (size_t)row * 128 + wp * 2)
                        : (W3r + (size_t)(row - 64) * 128 + wp * 2);
    float2 v = *(const float2*)p;
    __half2 h = __float22half2_rn(v);
    unsigned* dsts[5] = {g_w1l, g_w1r, g_w2l, g_w2r, g_w3c};
    dsts[tile][rem] = *(unsigned*)&h;
}

// ---------------- prep: x -> fp16 ----------------
__global__ void k_xprep(const float* __restrict__ x) {
    int i = blockIdx.x * blockDim.x + threadIdx.x;   // one float4 each
    if (i >= NN * 32) return;
    float4 v = ((const float4*)x)[i];
    __half2* o = (__half2*)g_xh + 2 * i;
    o[0] = __float22half2_rn(make_float2(v.x, v.y));
    o[1] = __float22half2_rn(make_float2(v.z, v.w));
}

// ---------------- mean aggregation (128-wide, half-warp per edge) ----------------
__device__ __forceinline__ void addu4(uint4 u, float* acc) {
    float2 f0 = __half22float2(*(__half2*)&u.x);
    float2 f1 = __half22float2(*(__half2*)&u.y);
    float2 f2 = __half22float2(*(__half2*)&u.z);
    float2 f3 = __half22float2(*(__half2*)&u.w);
    acc[0] += f0.x; acc[1] += f0.y; acc[2] += f1.x; acc[3] += f1.y;
    acc[4] += f2.x; acc[5] += f2.y; acc[6] += f3.x; acc[7] += f3.y;
}

__global__ void k_aggr128h(const __half* __restrict__ xh, __half* __restrict__ outh) {
    int wid = blockIdx.x * (blockDim.x >> 5) + (threadIdx.x >> 5);
    int lane = threadIdx.x & 31;
    if (wid >= NN) return;
    int beg = g_rowptr[wid], end = g_rowptr[wid + 1];
    int half = lane >> 4, sub = lane & 15;
    const uint4* base = (const uint4*)xh;    // 16 uint4 per 128-fp16 row
    float acc[8] = {0.f, 0.f, 0.f, 0.f, 0.f, 0.f, 0.f, 0.f};
    int j = beg;
    for (; j + 7 < end; j += 8) {            // 8 edges/warp/iter, MLP=4 per lane
        int e0 = g_csr[j + half * 4 + 0];
        int e1 = g_csr[j + half * 4 + 1];
        int e2 = g_csr[j + half * 4 + 2];
        int e3 = g_csr[j + half * 4 + 3];
        uint4 u0 = base[(size_t)e0 * 16 + sub];
        uint4 u1 = base[(size_t)e1 * 16 + sub];
        uint4 u2 = base[(size_t)e2 * 16 + sub];
        uint4 u3 = base[(size_t)e3 * 16 + sub];
        addu4(u0, acc); addu4(u1, acc); addu4(u2, acc); addu4(u3, acc);
    }
    for (; j + 1 < end; j += 2) {            // 2 edges/warp/iter
        int e = g_csr[j + half];
        uint4 u = base[(size_t)e * 16 + sub];
        addu4(u, acc);
    }
    if (j < end && half == 0) {
        uint4 u = base[(size_t)g_csr[j] * 16 + sub];
        addu4(u, acc);
    }
#pragma unroll
    for (int i = 0; i < 8; i++)
        acc[i] += __shfl_xor_sync(0xffffffffu, acc[i], 16);
    if (half == 0) {
        float inv = 1.f / fmaxf((float)(end - beg), 1.f);
        __half2 h0 = __float22half2_rn(make_float2(acc[0] * inv, acc[1] * inv));
        __half2 h1 = __float22half2_rn(make_float2(acc[2] * inv, acc[3] * inv));
        __half2 h2 = __float22half2_rn(make_float2(acc[4] * inv, acc[5] * inv));
        __half2 h3 = __float22half2_rn(make_float2(acc[6] * inv, acc[7] * inv));
        uint4 o = make_uint4(*(unsigned*)&h0, *(unsigned*)&h1,
                             *(unsigned*)&h2, *(unsigned*)&h3);
        ((uint4*)outh)[(size_t)wid * 16 + sub] = o;
    }
}

// ---------------- fused agg64 + add + log_softmax (warp per node) ----------------
__global__ void k_agg_lsm(const __half* __restrict__ t3h, const float* __restrict__ r3,
                          float* __restrict__ out) {
    int wid = blockIdx.x * (blockDim.x >> 5) + (threadIdx.x >> 5);
    int lane = threadIdx.x & 31;
    if (wid >= NN) return;
    int beg = g_rowptr[wid], end = g_rowptr[wid + 1];
    const unsigned* base = (const unsigned*)t3h;   // 32 half2 words per 64-fp16 row
    float a0 = 0.f, a1 = 0.f;
    int j = beg;
    for (; j + 3 < end; j += 4) {
        int s0 = g_csr[j], s1 = g_csr[j + 1], s2 = g_csr[j + 2], s3 = g_csr[j + 3];
        unsigned u0 = base[(size_t)s0 * 32 + lane];
        unsigned u1 = base[(size_t)s1 * 32 + lane];
        unsigned u2 = base[(size_t)s2 * 32 + lane];
        unsigned u3 = base[(size_t)s3 * 32 + lane];
        float2 f0 = __half22float2(*(__half2*)&u0);
        float2 f1 = __half22float2(*(__half2*)&u1);
        float2 f2 = __half22float2(*(__half2*)&u2);
        float2 f3 = __half22float2(*(__half2*)&u3);
        a0 += (f0.x + f1.x) + (f2.x + f3.x);
        a1 += (f0.y + f1.y) + (f2.y + f3.y);
    }
    for (; j < end; j++) {
        unsigned u0 = base[(size_t)g_csr[j] * 32 + lane];
        float2 f0 = __half22float2(*(__half2*)&u0);
        a0 += f0.x; a1 += f0.y;
    }
    float inv = 1.f / fmaxf((float)(end - beg), 1.f);
    float2 rv = *(const float2*)(r3 + (size_t)wid * 64 + lane * 2);
    float v0 = rv.x + a0 * inv;
    float v1 = rv.y + a1 * inv;
    float m = fmaxf(v0, v1);
#pragma unroll
    for (int o = 16; o > 0; o >>= 1) m = fmaxf(m, __shfl_xor_sync(0xffffffffu, m, o));
    float s = expf(v0 - m) + expf(v1 - m);
#pragma unroll
    for (int o = 16; o > 0; o >>= 1) s += __shfl_xor_sync(0xffffffffu, s, o);
    float l = m + logf(s);
    *(float2*)(out + (size_t)wid * 64 + lane * 2) = make_float2(v0 - l, v1 - l);
}

// ---------------- GEMM machinery: cp.async pipeline + fp16 MMA ----------------
#define MMA_F16(C, A, b0, b1)                                                 \
    asm volatile(                                                             \
        "mma.sync.aligned.m16n8k16.row.col.f32.f16.f16.f32 "                  \
        "{%0,%1,%2,%3},{%4,%5,%6,%7},{%8,%9},{%0,%1,%2,%3};"                  \
        : "+f"((C)[0]), "+f"((C)[1]), "+f"((C)[2]), "+f"((C)[3])              \
        : "r"((A)[0]), "r"((A)[1]), "r"((A)[2]), "r"((A)[3]),                 \
          "r"(b0), "r"(b1))

__device__ __forceinline__ uint32_t su32(const void* p) {
    uint32_t a;
    asm("{ .reg .u64 t; cvta.to.shared.u64 t, %1; cvt.u32.u64 %0, t; }" : "=r"(a) : "l"(p));
    return a;
}

#define SWZB(o) ((o) ^ (((o) >> 3) & 0x30))
#define STAGE_B 16384     // A+W: 2 x 128 rows x 64B (32 fp16 K-chunk)
#define STAGES 3
#define DSMEM  (STAGES * STAGE_B + 128)
#define DSMEM3 (4 * STAGE_B + 128)     // fused layer-2 kernel: 64KB tile space

__device__ __forceinline__ void issue_chunk(uint32_t sbase,
    const unsigned* __restrict__ A, const unsigned* __restrict__ W,
    int k0w, int row0, int t)
{
#pragma unroll
    for (int tn = 0; tn < 2; tn++) {
#pragma unroll
        for (int j = 0; j < 2; j++) {
            int idx = t + j * 256;
            int row = idx >> 2, c16 = idx & 3;
            uint32_t dstp = sbase + tn * 8192 + SWZB(row * 64 + c16 * 16);
            const unsigned* bp;
            int sz = 16;
            if (tn == 0) {
                int gr = row0 + row;
                if (gr >= NN) { sz = 0; gr = NN - 1; }
                bp = A + (size_t)gr * 64 + k0w + c16 * 4;
            } else {
                bp = W + (size_t)row * 64 + k0w + c16 * 4;
            }
            asm volatile("cp.async.cg.shared.global [%0], [%1], 16, %2;"
                         :: "r"(dstp), "l"(bp), "r"(sz) : "memory");
        }
    }
    asm volatile("cp.async.commit_group;" ::: "memory");
}

// MMA sweep over one staged chunk: 2 ksteps x 8nt x 2mt
__device__ __forceinline__ void mma_chunk(const char* Am, const char* Wm,
                                          float c[2][8][4], int wr, int wc,
                                          int g, int tg)
{
#pragma unroll
    for (int ks = 0; ks < 2; ks++) {
        const int kw = ks * 8;
        unsigned a[2][4];
#pragma unroll
        for (int mt = 0; mt < 2; mt++) {
            int r = wr * 32 + mt * 16 + g;
            a[mt][0] = *(const unsigned*)(Am + SWZB(r * 64 + (kw + tg) * 4));
            a[mt][1] = *(const unsigned*)(Am + SWZB((r + 8) * 64 + (kw + tg) * 4));
            a[mt][2] = *(const unsigned*)(Am + SWZB(r * 64 + (kw + tg + 4) * 4));
            a[mt][3] = *(const unsigned*)(Am + SWZB((r + 8) * 64 + (kw + tg + 4) * 4));
        }
#pragma unroll
        for (int nt = 0; nt < 8; nt++) {
            int n = wc * 64 + nt * 8 + g;
            unsigned b0 = *(const unsigned*)(Wm + SWZB(n * 64 + (kw + tg) * 4));
            unsigned b1 = *(const unsigned*)(Wm + SWZB(n * 64 + (kw + tg + 4) * 4));
#pragma unroll
            for (int mt = 0; mt < 2; mt++)
                MMA_F16(c[mt][nt], a[mt], b0, b1);
        }
    }
}

// ---------------- layer-1 dual GEMM + BN + ReLU -> fp16 ----------------
__global__ __launch_bounds__(256, 2) void k_gemm_dual(
    const unsigned* __restrict__ A0, const unsigned* __restrict__ W0,
    const unsigned* __restrict__ A1, const unsigned* __restrict__ W1,
    const float* __restrict__ bias, const float* __restrict__ gamma,
    const float* __restrict__ beta, const float* __restrict__ rmean,
    const float* __restrict__ rvar, __half* __restrict__ outh)
{
    extern __shared__ uint4 dyn4[];
    __shared__ float s_sc[128], s_sh[128];
    const int t = threadIdx.x;
    const int lane = t & 31, wid = t >> 5;
    const int wr = wid & 3, wc = wid >> 2;
    const int g = lane >> 2, tg = lane & 3;
    const int row0 = blockIdx.x * 128;

    uint32_t sb0 = su32(dyn4);
    uint32_t ab = (sb0 + 127u) & ~127u;
    const char* smbase = (const char*)dyn4 + (ab - sb0);

    if (t < 128) {
        float s = gamma[t] * rsqrtf(rvar[t] + 1e-5f);
        s_sc[t] = s;
        s_sh[t] = beta[t] + (bias[t] - rmean[t]) * s;
    }

    float c[2][8][4];
#pragma unroll
    for (int mt = 0; mt < 2; mt++)
#pragma unroll
        for (int nt = 0; nt < 8; nt++)
#pragma unroll
            for (int q = 0; q < 4; q++) c[mt][nt][q] = 0.f;

#pragma unroll
    for (int s = 0; s < STAGES; s++)
        issue_chunk(ab + s * STAGE_B, A0, W0, s * 16, row0, t);

#pragma unroll
    for (int cc = 0; cc < 8; cc++) {
        asm volatile("cp.async.wait_group 2;" ::: "memory");
        __syncthreads();
        const char* sm = smbase + (cc % 3) * STAGE_B;
        mma_chunk(sm, sm + 8192, c, wr, wc, g, tg);
        __syncthreads();
        if (cc + STAGES < 8) {
            int nc = cc + STAGES;
            int pass = nc >> 2;
            issue_chunk(ab + (nc % 3) * STAGE_B,
                        pass ? A1 : A0, pass ? W1 : W0, (nc & 3) * 16, row0, t);
        } else {
            asm volatile("cp.async.commit_group;" ::: "memory");
        }
    }

#pragma unroll
    for (int mt = 0; mt < 2; mt++) {
#pragma unroll
        for (int i = 0; i < 2; i++) {
            int r = row0 + wr * 32 + mt * 16 + g + i * 8;
            if (r >= NN) continue;
#pragma unroll
            for (int nt = 0; nt < 8; nt++) {
                int col = wc * 64 + nt * 8 + 2 * tg;
                float v0 = c[mt][nt][2 * i];
                float v1 = c[mt][nt][2 * i + 1];
                v0 = fmaxf(v0 * s_sc[col] + s_sh[col], 0.f);
                v1 = fmaxf(v1 * s_sc[col + 1] + s_sh[col + 1], 0.f);
                *(__half2*)(outh + (size_t)r * 128 + col) =
                    __float22half2_rn(make_float2(v0, v1));
            }
        }
    }
}

// ---------------- layer-2 dual GEMM + BN + ReLU fused with layer-3 GEMM ----------------
// phase 1: h2 = relu(bn2(agg@W2l + h1@W2r + b2)) -> smem tile (never global)
// phase 2: h2_tile @ [W3l;W3r]^T -> t3h (cols 0..63 fp16), r3 (cols 64..127 +b3)
__global__ __launch_bounds__(256, 2) void k_gemm_dual_l2(
    const unsigned* __restrict__ A0, const unsigned* __restrict__ W0,
    const unsigned* __restrict__ A1, const unsigned* __restrict__ W1,
    const float* __restrict__ bias, const float* __restrict__ gamma,
    const float* __restrict__ beta, const float* __restrict__ rmean,
    const float* __restrict__ rvar,
    const unsigned* __restrict__ W3, const float* __restrict__ b3,
    __half* __restrict__ t3h, float* __restrict__ r3)
{
    extern __shared__ uint4 dyn4[];
    __shared__ float s_sc[128], s_sh[128];
    const int t = threadIdx.x;
    const int lane = t & 31, wid = t >> 5;
    const int wr = wid & 3, wc = wid >> 2;
    const int g = lane >> 2, tg = lane & 3;
    const int row0 = blockIdx.x * 128;

    uint32_t sb0 = su32(dyn4);
    uint32_t ab = (sb0 + 127u) & ~127u;
    char* smbase = (char*)dyn4 + (ab - sb0);

    if (t < 128) {
        float s = gamma[t] * rsqrtf(rvar[t] + 1e-5f);
        s_sc[t] = s;
        s_sh[t] = beta[t] + (bias[t] - rmean[t]) * s;
    }

    float c[2][8][4];
#pragma unroll
    for (int mt = 0; mt < 2; mt++)
#pragma unroll
        for (int nt = 0; nt < 8; nt++)
#pragma unroll
            for (int q = 0; q < 4; q++) c[mt][nt][q] = 0.f;

    // ---- phase 1: pipelined dual GEMM (same as layer-1) ----
#pragma unroll
    for (int s = 0; s < STAGES; s++)
        issue_chunk(ab + s * STAGE_B, A0, W0, s * 16, row0, t);

#pragma unroll
    for (int cc = 0; cc < 8; cc++) {
        asm volatile("cp.async.wait_group 2;" ::: "memory");
        __syncthreads();
        const char* sm = smbase + (cc % 3) * STAGE_B;
        mma_chunk(sm, sm + 8192, c, wr, wc, g, tg);
        __syncthreads();
        if (cc + STAGES < 8) {
            int nc = cc + STAGES;
            int pass = nc >> 2;
            issue_chunk(ab + (nc % 3) * STAGE_B,
                        pass ? A1 : A0, pass ? W1 : W0, (nc & 3) * 16, row0, t);
        } else {
            asm volatile("cp.async.commit_group;" ::: "memory");
        }
    }
    asm volatile("cp.async.wait_group 0;" ::: "memory");
    __syncthreads();

    // ---- stage W3c (4 chunks, 32KB) into smem upper half via cp.async ----
#pragma unroll
    for (int kc = 0; kc < 4; kc++) {
#pragma unroll
        for (int j = 0; j < 2; j++) {
            int idx = t + j * 256;
            int row = idx >> 2, c16 = idx & 3;
            uint32_t dstp = ab + 32768 + kc * 8192 + SWZB(row * 64 + c16 * 16);
            const unsigned* bp = W3 + (size_t)row * 64 + kc * 16 + c16 * 4;
            asm volatile("cp.async.cg.shared.global [%0], [%1], 16, 16;"
                         :: "r"(dstp), "l"(bp) : "memory");
        }
    }
    asm volatile("cp.async.commit_group;" ::: "memory");

    // ---- BN + ReLU -> fp16 h2 tile into smem lower half (stage-chunk layout) ----
#pragma unroll
    for (int mt = 0; mt < 2; mt++) {
#pragma unroll
        for (int i = 0; i < 2; i++) {
            int rl = wr * 32 + mt * 16 + g + i * 8;   // local row 0..127
#pragma unroll
            for (int nt = 0; nt < 8; nt++) {
                int col = wc * 64 + nt * 8 + 2 * tg;  // K index of h2, 0..127
                float v0 = fmaxf(c[mt][nt][2 * i] * s_sc[col] + s_sh[col], 0.f);
                float v1 = fmaxf(c[mt][nt][2 * i + 1] * s_sc[col + 1] + s_sh[col + 1], 0.f);
                __half2 h = __float22half2_rn(make_float2(v0, v1));
                int kc = col >> 5;
                int off = kc * 8192 + SWZB(rl * 64 + ((col & 31) >> 1) * 4);
                *(unsigned*)(smbase + off) = *(unsigned*)&h;
            }
        }
    }
    asm volatile("cp.async.wait_group 0;" ::: "memory");
    __syncthreads();

    // ---- phase 2: h2_tile @ W3c over K=128 (4 chunks), accumulators reused ----
#pragma unroll
    for (int mt = 0; mt < 2; mt++)
#pragma unroll
        for (int nt = 0; nt < 8; nt++)
#pragma unroll
            for (int q = 0; q < 4; q++) c[mt][nt][q] = 0.f;

#pragma unroll
    for (int kc = 0; kc < 4; kc++)
        mma_chunk(smbase + kc * 8192, smbase + 32768 + kc * 8192, c, wr, wc, g, tg);

    // ---- epilogue: cols 0..63 -> t3h (fp16), 64..127 -> r3 + b3 ----
#pragma unroll
    for (int mt = 0; mt < 2; mt++) {
#pragma unroll
        for (int i = 0; i < 2; i++) {
            int r = row0 + wr * 32 + mt * 16 + g + i * 8;
            if (r >= NN) continue;
#pragma unroll
            for (int nt = 0; nt < 8; nt++) {
                int col = wc * 64 + nt * 8 + 2 * tg;
                float v0 = c[mt][nt][2 * i];
                float v1 = c[mt][nt][2 * i + 1];
                if (col < 64) {
                    *(__half2*)(t3h + (size_t)r * 64 + col) =
                        __float22half2_rn(make_float2(v0, v1));
                } else {
                    int cc2 = col - 64;
                    v0 += b3[cc2]; v1 += b3[cc2 + 1];
                    *(float2*)(r3 + (size_t)r * 64 + cc2) = make_float2(v0, v1);
                }
            }
        }
    }
}

// ---------------- launch ----------------
extern "C" void kernel_launch(void* const* d_in, const int* in_sizes, int n_in,
                              void* d_out, int out_size) {
    const float* x   = (const float*)d_in[0];
    const int*   src = (const int*)d_in[1];
    const int*   dst = (const int*)d_in[2];
    const float* W1l = (const float*)d_in[3];
    const float* W1r = (const float*)d_in[4];
    const float* b1  = (const float*)d_in[5];
    const float* g1  = (const float*)d_in[6];
    const float* be1 = (const float*)d_in[7];
    const float* rm1 = (const float*)d_in[8];
    const float* rv1 = (const float*)d_in[9];
    const float* W2l = (const float*)d_in[10];
    const float* W2r = (const float*)d_in[11];
    const float* b2  = (const float*)d_in[12];
    const float* g2  = (const float*)d_in[13];
    const float* be2 = (const float*)d_in[14];
    const float* rm2 = (const float*)d_in[15];
    const float* rv2 = (const float*)d_in[16];
    const float* W3l = (const float*)d_in[17];
    const float* W3r = (const float*)d_in[18];
    const float* b3  = (const float*)d_in[19];
    float* out = (float*)d_out;
    int E = in_sizes[1];

    __half *p_xh, *p_aggh, *p_h1h, *p_t3h;
    float *p_r3;
    unsigned *p_w1l, *p_w1r, *p_w2l, *p_w2r, *p_w3c;
    cudaGetSymbolAddress((void**)&p_xh,   g_xh);
    cudaGetSymbolAddress((void**)&p_aggh, g_aggh);
    cudaGetSymbolAddress((void**)&p_h1h,  g_h1h);
    cudaGetSymbolAddress((void**)&p_t3h,  g_t3h);
    cudaGetSymbolAddress((void**)&p_r3,   g_r3);
    cudaGetSymbolAddress((void**)&p_w1l,  g_w1l);
    cudaGetSymbolAddress((void**)&p_w1r,  g_w1r);
    cudaGetSymbolAddress((void**)&p_w2l,  g_w2l);
    cudaGetSymbolAddress((void**)&p_w2r,  g_w2r);
    cudaGetSymbolAddress((void**)&p_w3c,  g_w3c);

    cudaFuncSetAttribute(k_gemm_dual,
                         cudaFuncAttributeMaxDynamicSharedMemorySize, DSMEM);
    cudaFuncSetAttribute(k_gemm_dual_l2,
                         cudaFuncAttributeMaxDynamicSharedMemorySize, DSMEM3);

    // CSR build
    k_hist<<<(E + 255) / 256, 256>>>(dst, E);
    k_scan1<<<NBLK_SCAN, 1024>>>();
    k_scan2<<<1, 128>>>();
    k_scan3<<<(NN + 1 + 255) / 256, 256>>>(E);
    k_scatter<<<(E + 255) / 256, 256>>>(src, dst, E);

    // one-time fp16 prep
    k_wprep<<<(5 * 8192 + 255) / 256, 256>>>(W1l, W1r, W2l, W2r, W3l, W3r);
    k_xprep<<<(NN * 32 + 255) / 256, 256>>>(x);

    const int gemm_blocks = (NN + 127) / 128;

    // layer 1
    k_aggr128h<<<NN / 8, 256>>>(p_xh, p_aggh);
    k_gemm_dual<<<gemm_blocks, 256, DSMEM>>>(
        (const unsigned*)p_aggh, p_w1l, (const unsigned*)p_xh, p_w1r,
        b1, g1, be1, rm1, rv1, p_h1h);
    // layer 2 + layer-3 GEMM fused
    k_aggr128h<<<NN / 8, 256>>>(p_h1h, p_aggh);
    k_gemm_dual_l2<<<gemm_blocks, 256, DSMEM3>>>(
        (const unsigned*)p_aggh, p_w2l, (const unsigned*)p_h1h, p_w2r,
        b2, g2, be2, rm2, rv2, p_w3c, b3, p_t3h, p_r3);
    // layer 3 aggregation + log_softmax fused
    k_agg_lsm<<<NN / 8, 256>>>(p_t3h, p_r3, out);
}